// round 12
// baseline (speedup 1.0000x reference)
#include <cuda_runtime.h>
#include <math.h>
#include <stdint.h>

#define Bb   4
#define Tt   1024
#define Cc   768
#define Hh   12
#define Ss   64
#define FFf  3072
#define HIDh 2048
#define Mm   (Bb*Tt)
#define NTOT (Mm*Cc)
#define BHn  (Bb*Hh)

// ---------- fp64 scratch (static, no allocs) ----------
__device__ double g_h   [Mm*Cc];
__device__ double g_q   [Mm*Cc];
__device__ double g_k   [Mm*Cc];
__device__ double g_v   [Mm*Cc];
__device__ double g_rq  [Mm*Cc];
__device__ double g_rk  [Mm*Cc];
__device__ double g_vt  [Mm*Cc];
__device__ double g_sc  [(size_t)BHn*Tt*Tt];
__device__ double g_attn[Mm*Cc];
__device__ double g_out1[Mm*Cc];
__device__ double g_u   [Mm*FFf];
__device__ double g_wx  [Mm*HIDh];
__device__ double g_vx  [Mm*HIDh];
__device__ double g_ff  [Mm*FFf];
__device__ double g_wp  [3*Cc*Cc];
__device__ double g_part[1024];
__device__ double g_scale[1];

// ---------- reductions ----------
template<typename T>
__global__ void sumsq_partial(const T* __restrict__ x, int n, double* __restrict__ part)
{
    double s = 0.0;
    for (int i = blockIdx.x*256 + threadIdx.x; i < n; i += gridDim.x*256) {
        double v = (double)x[i]; s += v*v;
    }
    #pragma unroll
    for (int o = 16; o > 0; o >>= 1) s += __shfl_xor_sync(0xffffffffu, s, o);
    __shared__ double sh[8];
    if ((threadIdx.x & 31) == 0) sh[threadIdx.x >> 5] = s;
    __syncthreads();
    if (threadIdx.x == 0) {
        double t = 0.0;
        #pragma unroll
        for (int w = 0; w < 8; w++) t += sh[w];
        part[blockIdx.x] = t;
    }
}

__global__ void finalize_scale(const double* __restrict__ part, int g, double invn, double* __restrict__ scale)
{
    double s = 0.0;
    for (int i = threadIdx.x; i < g; i += 256) s += part[i];
    #pragma unroll
    for (int o = 16; o > 0; o >>= 1) s += __shfl_xor_sync(0xffffffffu, s, o);
    __shared__ double sh[8];
    if ((threadIdx.x & 31) == 0) sh[threadIdx.x >> 5] = s;
    __syncthreads();
    if (threadIdx.x == 0) {
        double t = 0.0;
        for (int w = 0; w < 8; w++) t += sh[w];
        scale[0] = 1.0 / sqrt(1e-6 + t * invn);
    }
}

template<typename T>
__global__ void apply_rms(const T* __restrict__ x, const double* __restrict__ scale,
                          const float* __restrict__ g, double* __restrict__ out, int n)
{
    int i = blockIdx.x*256 + threadIdx.x;
    if (i < n) out[i] = (double)x[i] * scale[0] * (double)g[i % Cc];
}

// ---------- pack W_{q,k,v}: [H,C,S] -> [C, H*S], to double ----------
__global__ void pack_qkv(const float* __restrict__ Wq, const float* __restrict__ Wk,
                         const float* __restrict__ Wv, double* __restrict__ Wp)
{
    int i = blockIdx.x*256 + threadIdx.x;
    const int n = Hh*Cc*Ss;
    if (i >= n) return;
    int s = i % Ss; int r = i / Ss; int c = r % Cc; int h = r / Cc;
    int oc = c*Cc + h*Ss + s;
    Wp[oc]       = (double)Wq[i];
    Wp[n + oc]   = (double)Wk[i];
    Wp[2*n + oc] = (double)Wv[i];
}

// ---------- fp64 GEMM: C = A[MxK]*B[KxN] (+bias)(+res), 64x64 tiles ----------
template<typename TB, typename TR, typename TC, bool BIAS, bool RES>
__global__ __launch_bounds__(256) void dgemm64(
    const double* __restrict__ A, const TB* __restrict__ B,
    const float* __restrict__ bias, const TR* __restrict__ R,
    TC* __restrict__ C, int M, int N, int K)
{
    __shared__ double As[8][65];
    __shared__ double Bs[8][65];
    const int tid = threadIdx.x;
    const int bm = blockIdx.y * 64;
    const int bn = blockIdx.x * 64;
    const int tx = tid & 15;
    const int ty = tid >> 4;

    double acc[4][4];
    #pragma unroll
    for (int i = 0; i < 4; i++)
        #pragma unroll
        for (int j = 0; j < 4; j++) acc[i][j] = 0.0;

    for (int k0 = 0; k0 < K; k0 += 8) {
        __syncthreads();
        for (int l = tid; l < 512; l += 256) {
            int row = l >> 3, kk = l & 7;
            As[kk][row] = A[(size_t)(bm + row) * K + k0 + kk];
            int r = l >> 6, c = l & 63;
            Bs[r][c] = (double)B[(size_t)(k0 + r) * N + bn + c];
        }
        __syncthreads();
        #pragma unroll
        for (int kk = 0; kk < 8; kk++) {
            double ar[4], br[4];
            #pragma unroll
            for (int i = 0; i < 4; i++) ar[i] = As[kk][ty*4 + i];
            #pragma unroll
            for (int j = 0; j < 4; j++) br[j] = Bs[kk][tx*4 + j];
            #pragma unroll
            for (int i = 0; i < 4; i++)
                #pragma unroll
                for (int j = 0; j < 4; j++)
                    acc[i][j] += ar[i] * br[j];
        }
    }

    #pragma unroll
    for (int i = 0; i < 4; i++) {
        size_t rbase = (size_t)(bm + ty*4 + i) * N;
        #pragma unroll
        for (int j = 0; j < 4; j++) {
            int c = bn + tx*4 + j;
            double v = acc[i][j];
            if (BIAS) v += (double)bias[c];
            if (RES)  v += (double)R[rbase + c];
            C[rbase + c] = (TC)v;
        }
    }
}

// ---------- RoPE + layout transform (fp64) ----------
__global__ void rope_reorder(const double* __restrict__ q, const double* __restrict__ k,
                             const double* __restrict__ v,
                             double* __restrict__ rq, double* __restrict__ rk,
                             double* __restrict__ vt)
{
    int p = blockIdx.x*256 + threadIdx.x;
    if (p >= Bb*Tt*Hh*32) return;
    int j = p & 31;  int r = p >> 5;
    int h = r % Hh;  r /= Hh;
    int t = r % Tt;  int b = r / Tt;
    size_t in  = ((size_t)(b*Tt + t))*Cc + h*Ss + 2*j;
    size_t out = (((size_t)(b*Hh + h))*Tt + t)*Ss + 2*j;
    double theta = exp(-0.5756462732485115 * (double)j);   // 10000^{-j/16}
    double ang = (double)t * theta;
    double sn, cs;
    sincos(ang, &sn, &cs);
    double q0 = q[in], q1 = q[in+1];
    rq[out]   = q0*cs - q1*sn;
    rq[out+1] = q1*cs + q0*sn;
    double k0 = k[in], k1 = k[in+1];
    rk[out]   = k0*cs - k1*sn;
    rk[out+1] = k1*cs + k0*sn;
    vt[out]   = v[in];
    vt[out+1] = v[in+1];
}

// ---------- scores: S = scale * Q K^T, 32x32 tiles, causal-skipped ----------
__global__ __launch_bounds__(256) void attn_scores(const double* __restrict__ Q,
    const double* __restrict__ Kv, double* __restrict__ Sc)
{
    int bh = blockIdx.z;
    int t0 = blockIdx.y * 32;
    int k0 = blockIdx.x * 32;
    if (k0 > t0) return;                       // fully masked tile
    __shared__ double Qs[32][65];
    __shared__ double Ks[32][65];
    const double* Qb = Q  + ((size_t)bh*Tt + t0) * Ss;
    const double* Kb = Kv + ((size_t)bh*Tt + k0) * Ss;
    int tid = threadIdx.x;
    for (int l = tid; l < 32*64; l += 256) {
        int row = l >> 6, s = l & 63;
        Qs[row][s] = Qb[(size_t)row*Ss + s];
        Ks[row][s] = Kb[(size_t)row*Ss + s];
    }
    __syncthreads();
    int tx = tid & 15, ty = tid >> 4;
    double acc[2][2];
    acc[0][0] = acc[0][1] = acc[1][0] = acc[1][1] = 0.0;
    for (int s = 0; s < 64; s++) {
        double ar[2], br[2];
        ar[0] = Qs[ty*2][s];   ar[1] = Qs[ty*2+1][s];
        br[0] = Ks[tx*2][s];   br[1] = Ks[tx*2+1][s];
        acc[0][0] += ar[0]*br[0]; acc[0][1] += ar[0]*br[1];
        acc[1][0] += ar[1]*br[0]; acc[1][1] += ar[1]*br[1];
    }
    const double scale = 0.03608439182435161;  // 768^-0.5
    #pragma unroll
    for (int i = 0; i < 2; i++) {
        size_t off = (size_t)bh*Tt*Tt + (size_t)(t0 + ty*2 + i)*Tt + k0 + tx*2;
        Sc[off]   = acc[i][0]*scale;
        Sc[off+1] = acc[i][1]*scale;
    }
}

// ---------- causal softmax (fp64) ----------
__global__ void softmax_causal(double* __restrict__ Sc)
{
    int row = blockIdx.x;
    int t = row & (Tt - 1);
    double* p = Sc + (size_t)row * Tt;
    int len = t + 1;
    int tid = threadIdx.x;
    __shared__ double sh[8];

    double m = -1e300;
    for (int k = tid; k < len; k += 256) m = fmax(m, p[k]);
    #pragma unroll
    for (int o = 16; o > 0; o >>= 1) m = fmax(m, __shfl_xor_sync(0xffffffffu, m, o));
    if ((tid & 31) == 0) sh[tid >> 5] = m;
    __syncthreads();
    m = sh[0];
    #pragma unroll
    for (int w = 1; w < 8; w++) m = fmax(m, sh[w]);
    __syncthreads();

    double sum = 0.0;
    for (int k = tid; k < len; k += 256) {
        double e = exp(p[k] - m);
        p[k] = e;
        sum += e;
    }
    #pragma unroll
    for (int o = 16; o > 0; o >>= 1) sum += __shfl_xor_sync(0xffffffffu, sum, o);
    if ((tid & 31) == 0) sh[tid >> 5] = sum;
    __syncthreads();
    sum = 0.0;
    #pragma unroll
    for (int w = 0; w < 8; w++) sum += sh[w];
    double inv = 1.0 / sum;
    for (int k = tid; k < len; k += 256) p[k] *= inv;
    for (int k = len + tid; k < Tt; k += 256) p[k] = 0.0;
}

// ---------- attn output: O = P V -> [b,t,(h,s)] (fp64) ----------
__global__ __launch_bounds__(256) void attn_av(const double* __restrict__ P,
     const double* __restrict__ V, double* __restrict__ O)
{
    int bh = blockIdx.y;
    int b = bh / Hh, h = bh % Hh;
    int t0 = blockIdx.x * 64;
    __shared__ double Ps[64][17];
    __shared__ double Vs[16][65];
    const double* Pb = P + ((size_t)bh*Tt + t0) * Tt;
    const double* Vb = V + (size_t)bh*Tt*Ss;
    int tid = threadIdx.x;
    int tx = tid & 15, ty = tid >> 4;
    double acc[4][4];
    #pragma unroll
    for (int i = 0; i < 4; i++)
        #pragma unroll
        for (int j = 0; j < 4; j++) acc[i][j] = 0.0;

    int kmax = t0 + 64;
    for (int k0 = 0; k0 < kmax; k0 += 16) {
        __syncthreads();
        {
            int r = tid >> 2; int c4 = (tid & 3) * 4;
            #pragma unroll
            for (int m2 = 0; m2 < 4; m2++)
                Ps[r][c4+m2] = Pb[(size_t)r*Tt + k0 + c4 + m2];
            int r2 = tid >> 4; int c2 = (tid & 15) * 4;
            #pragma unroll
            for (int m2 = 0; m2 < 4; m2++)
                Vs[r2][c2+m2] = Vb[(size_t)(k0 + r2)*Ss + c2 + m2];
        }
        __syncthreads();
        #pragma unroll
        for (int kk = 0; kk < 16; kk++) {
            double br[4];
            #pragma unroll
            for (int j = 0; j < 4; j++) br[j] = Vs[kk][tx*4 + j];
            double ar[4];
            #pragma unroll
            for (int i = 0; i < 4; i++) ar[i] = Ps[ty*4+i][kk];
            #pragma unroll
            for (int i = 0; i < 4; i++)
                #pragma unroll
                for (int j = 0; j < 4; j++) acc[i][j] += ar[i]*br[j];
        }
    }
    #pragma unroll
    for (int i = 0; i < 4; i++) {
        int t = t0 + ty*4 + i;
        size_t o = ((size_t)b*Tt + t)*Cc + h*Ss + tx*4;
        #pragma unroll
        for (int j = 0; j < 4; j++) O[o + j] = acc[i][j];
    }
}

// ---------- SwiGLU elementwise (fp64) ----------
__global__ void silu_mul(const double* __restrict__ wx, const double* __restrict__ vx,
                         double* __restrict__ out, int n)
{
    int i = blockIdx.x*256 + threadIdx.x;
    if (i < n) {
        double v = vx[i];
        double sig = 1.0 / (1.0 + exp(-v));
        out[i] = wx[i] * (v * sig);
    }
}

// ---------- host ----------
static void* symaddr(const void* sym)
{
    void* p = nullptr;
    cudaGetSymbolAddress(&p, sym);
    return p;
}

extern "C" void kernel_launch(void* const* d_in, const int* in_sizes, int n_in,
                              void* d_out, int out_size)
{
    const float* x  = (const float*)d_in[0];
    const float* Wq = (const float*)d_in[1];
    const float* Wk = (const float*)d_in[2];
    const float* Wv = (const float*)d_in[3];
    const float* Wo = (const float*)d_in[4];
    const float* g1 = (const float*)d_in[5];
    const float* g2 = (const float*)d_in[6];
    const float* W1 = (const float*)d_in[7];
    const float* b1 = (const float*)d_in[8];
    const float* Ww = (const float*)d_in[9];
    const float* bw = (const float*)d_in[10];
    const float* Wg = (const float*)d_in[11];
    const float* bg = (const float*)d_in[12];
    const float* Wd = (const float*)d_in[13];
    const float* bd = (const float*)d_in[14];
    const float* W2 = (const float*)d_in[15];
    const float* b2 = (const float*)d_in[16];
    float* out = (float*)d_out;

    double* p_h    = (double*)symaddr(g_h);
    double* p_q    = (double*)symaddr(g_q);
    double* p_k    = (double*)symaddr(g_k);
    double* p_v    = (double*)symaddr(g_v);
    double* p_rq   = (double*)symaddr(g_rq);
    double* p_rk   = (double*)symaddr(g_rk);
    double* p_vt   = (double*)symaddr(g_vt);
    double* p_sc   = (double*)symaddr(g_sc);
    double* p_attn = (double*)symaddr(g_attn);
    double* p_out1 = (double*)symaddr(g_out1);
    double* p_u    = (double*)symaddr(g_u);
    double* p_wx   = (double*)symaddr(g_wx);
    double* p_vx   = (double*)symaddr(g_vx);
    double* p_ff   = (double*)symaddr(g_ff);
    double* p_wp   = (double*)symaddr(g_wp);
    double* p_part = (double*)symaddr(g_part);
    double* p_scal = (double*)symaddr(g_scale);

    const double invn = 1.0 / (double)NTOT;

    // rms1 on x (float input)
    sumsq_partial<float><<<1024, 256>>>(x, NTOT, p_part);
    finalize_scale<<<1, 256>>>(p_part, 1024, invn, p_scal);
    apply_rms<float><<<NTOT/256, 256>>>(x, p_scal, g1, p_h, NTOT);

    // QKV
    pack_qkv<<<(Hh*Cc*Ss + 255)/256, 256>>>(Wq, Wk, Wv, p_wp);
    dgemm64<double,float,double,false,false><<<dim3(Cc/64, Mm/64), 256>>>(p_h, p_wp,           nullptr, nullptr, p_q, Mm, Cc, Cc);
    dgemm64<double,float,double,false,false><<<dim3(Cc/64, Mm/64), 256>>>(p_h, p_wp + Cc*Cc,   nullptr, nullptr, p_k, Mm, Cc, Cc);
    dgemm64<double,float,double,false,false><<<dim3(Cc/64, Mm/64), 256>>>(p_h, p_wp + 2*Cc*Cc, nullptr, nullptr, p_v, Mm, Cc, Cc);
    rope_reorder<<<(Bb*Tt*Hh*32)/256, 256>>>(p_q, p_k, p_v, p_rq, p_rk, p_vt);

    // attention
    attn_scores<<<dim3(Tt/32, Tt/32, BHn), 256>>>(p_rq, p_rk, p_sc);
    softmax_causal<<<BHn*Tt, 256>>>(p_sc);
    attn_av<<<dim3(Tt/64, BHn), 256>>>(p_sc, p_vt, p_attn);
    // out1 = x + attn @ Wo   (A double, B float, residual float, C double)
    dgemm64<float,float,double,false,true><<<dim3(Cc/64, Mm/64), 256>>>(p_attn, Wo, nullptr, x, p_out1, Mm, Cc, Cc);

    // rms2 on out1 (double)
    sumsq_partial<double><<<1024, 256>>>(p_out1, NTOT, p_part);
    finalize_scale<<<1, 256>>>(p_part, 1024, invn, p_scal);
    apply_rms<double><<<NTOT/256, 256>>>(p_out1, p_scal, g2, p_h, NTOT);

    // MLP
    dgemm64<float,float,double,true,false><<<dim3(FFf/64, Mm/64), 256>>>(p_h,  W1, b1, nullptr, p_u,  Mm, FFf,  Cc);
    dgemm64<float,float,double,true,false><<<dim3(HIDh/64, Mm/64), 256>>>(p_u, Ww, bw, nullptr, p_wx, Mm, HIDh, FFf);
    dgemm64<float,float,double,true,false><<<dim3(HIDh/64, Mm/64), 256>>>(p_u, Wg, bg, nullptr, p_vx, Mm, HIDh, FFf);
    silu_mul<<<(Mm*HIDh)/256, 256>>>(p_wx, p_vx, p_wx, Mm*HIDh);
    dgemm64<float,float,double,true,false><<<dim3(FFf/64, Mm/64), 256>>>(p_wx, Wd, bd, nullptr, p_ff, Mm, FFf, HIDh);
    // out = out1 + ff @ W2 + b2   (write float to d_out)
    dgemm64<float,double,float,true,true><<<dim3(Cc/64, Mm/64), 256>>>(p_ff, W2, b2, p_out1, out, Mm, Cc, FFf);
}

// round 13
// speedup vs baseline: 3.5152x; 3.5152x over previous
#include <cuda_runtime.h>
#include <cuda_bf16.h>
#include <math.h>
#include <stdint.h>

#define Bb   4
#define Tt   1024
#define Cc   768
#define Hh   12
#define Ss   64
#define FFf  3072
#define HIDh 2048
#define Mm   (Bb*Tt)
#define NTOT (Mm*Cc)
#define BHn  (Bb*Hh)

__device__ float g_h   [Mm*Cc];
__device__ float g_q   [Mm*Cc];
__device__ float g_k   [Mm*Cc];
__device__ float g_v   [Mm*Cc];
__device__ float g_rq  [Mm*Cc];
__device__ float g_rk  [Mm*Cc];
__device__ float g_vt  [Mm*Cc];
__device__ float g_sc  [(size_t)BHn*Tt*Tt];
__device__ float g_attn[Mm*Cc];
__device__ float g_out1[Mm*Cc];
__device__ float g_u   [Mm*FFf];
__device__ float g_wx  [Mm*HIDh];
__device__ float g_vx  [Mm*HIDh];
__device__ float g_ff  [Mm*FFf];
__device__ float g_wp  [3*Cc*Cc];
__device__ float g_part[1024];
__device__ float g_scale[1];

// NOTE: harness builds with --use_fast_math. All transcendentals/divisions that
// feed the result go through DOUBLE (unaffected by fast-math float rewrites).

__global__ void sumsq_partial(const float* __restrict__ x, int n, float* __restrict__ part)
{
    float s = 0.f;
    for (int i = blockIdx.x*256 + threadIdx.x; i < n; i += gridDim.x*256) {
        float v = x[i]; s += v*v;
    }
    #pragma unroll
    for (int o = 16; o > 0; o >>= 1) s += __shfl_xor_sync(0xffffffffu, s, o);
    __shared__ float sh[8];
    if ((threadIdx.x & 31) == 0) sh[threadIdx.x >> 5] = s;
    __syncthreads();
    if (threadIdx.x == 0) {
        float t = 0.f;
        #pragma unroll
        for (int w = 0; w < 8; w++) t += sh[w];
        part[blockIdx.x] = t;
    }
}

__global__ void finalize_scale(const float* __restrict__ part, int g, float invn, float* __restrict__ scale)
{
    float s = 0.f;
    for (int i = threadIdx.x; i < g; i += 256) s += part[i];
    #pragma unroll
    for (int o = 16; o > 0; o >>= 1) s += __shfl_xor_sync(0xffffffffu, s, o);
    __shared__ float sh[8];
    if ((threadIdx.x & 31) == 0) sh[threadIdx.x >> 5] = s;
    __syncthreads();
    if (threadIdx.x == 0) {
        double t = 0.0;
        for (int w = 0; w < 8; w++) t += (double)sh[w];
        scale[0] = (float)(1.0 / sqrt(1e-6 + t * (double)invn));
    }
}

__global__ void apply_rms(const float* __restrict__ x, const float* __restrict__ scale,
                          const float* __restrict__ g, float* __restrict__ out, int n)
{
    int i = blockIdx.x*256 + threadIdx.x;
    if (i < n) out[i] = x[i] * scale[0] * g[i % Cc];
}

__global__ void pack_qkv(const float* __restrict__ Wq, const float* __restrict__ Wk,
                         const float* __restrict__ Wv, float* __restrict__ Wp)
{
    int i = blockIdx.x*256 + threadIdx.x;
    const int n = Hh*Cc*Ss;
    if (i >= n) return;
    int s = i % Ss; int r = i / Ss; int c = r % Cc; int h = r / Cc;
    int oc = c*Cc + h*Ss + s;
    Wp[oc]       = Wq[i];
    Wp[n + oc]   = Wk[i];
    Wp[2*n + oc] = Wv[i];
}

template<bool BIAS, bool RES>
__global__ __launch_bounds__(256) void sgemm128(
    const float* __restrict__ A, const float* __restrict__ B,
    const float* __restrict__ bias, const float* __restrict__ R,
    float* __restrict__ C, int M, int N, int K)
{
    __shared__ float As[8][128];
    __shared__ float Bs[8][128];
    const int tid = threadIdx.x;
    const int bm = blockIdx.y * 128;
    const int bn = blockIdx.x * 128;

    const int a_row = tid >> 1;
    const int a_k   = (tid & 1) * 4;
    const int b_row = tid >> 5;
    const int b_col = (tid & 31) * 4;

    const int tx = tid & 15;
    const int ty = tid >> 4;
    const int row0 = ty * 8;
    const int col0 = tx * 8;

    const float* Aptr = A + (size_t)(bm + a_row) * K + a_k;
    const float* Bptr = B + (size_t)b_row * N + bn + b_col;

    float acc[8][8];
    #pragma unroll
    for (int i = 0; i < 8; i++)
        #pragma unroll
        for (int j = 0; j < 8; j++) acc[i][j] = 0.f;

    for (int k0 = 0; k0 < K; k0 += 8) {
        float4 av = *(const float4*)Aptr;
        float4 bv = *(const float4*)Bptr;
        Aptr += 8; Bptr += (size_t)8 * N;
        __syncthreads();
        As[a_k+0][a_row] = av.x;
        As[a_k+1][a_row] = av.y;
        As[a_k+2][a_row] = av.z;
        As[a_k+3][a_row] = av.w;
        *(float4*)&Bs[b_row][b_col] = bv;
        __syncthreads();
        #pragma unroll
        for (int k = 0; k < 8; k++) {
            float4 a0 = *(const float4*)&As[k][row0];
            float4 a1 = *(const float4*)&As[k][row0+4];
            float4 b0 = *(const float4*)&Bs[k][col0];
            float4 b1 = *(const float4*)&Bs[k][col0+4];
            float ar[8] = {a0.x,a0.y,a0.z,a0.w,a1.x,a1.y,a1.z,a1.w};
            float br[8] = {b0.x,b0.y,b0.z,b0.w,b1.x,b1.y,b1.z,b1.w};
            #pragma unroll
            for (int i = 0; i < 8; i++)
                #pragma unroll
                for (int j = 0; j < 8; j++)
                    acc[i][j] += ar[i] * br[j];
        }
    }

    #pragma unroll
    for (int i = 0; i < 8; i++) {
        size_t r = (size_t)(bm + row0 + i) * N;
        #pragma unroll
        for (int j = 0; j < 8; j += 4) {
            int c = bn + col0 + j;
            float4 v = make_float4(acc[i][j], acc[i][j+1], acc[i][j+2], acc[i][j+3]);
            if (BIAS) {
                float4 bb = *(const float4*)&bias[c];
                v.x += bb.x; v.y += bb.y; v.z += bb.z; v.w += bb.w;
            }
            if (RES) {
                float4 rr = *(const float4*)&R[r + c];
                v.x += rr.x; v.y += rr.y; v.z += rr.z; v.w += rr.w;
            }
            *(float4*)&C[r + c] = v;
        }
    }
}

// RoPE: angle + sincos computed in DOUBLE (fast-math-proof), results cast to f32
__global__ void rope_reorder(const float* __restrict__ q, const float* __restrict__ k,
                             const float* __restrict__ v,
                             float* __restrict__ rq, float* __restrict__ rk,
                             float* __restrict__ vt)
{
    int p = blockIdx.x*256 + threadIdx.x;
    if (p >= Bb*Tt*Hh*32) return;
    int j = p & 31;  int r = p >> 5;
    int h = r % Hh;  r /= Hh;
    int t = r % Tt;  int b = r / Tt;
    size_t in  = ((size_t)(b*Tt + t))*Cc + h*Ss + 2*j;
    size_t out = (((size_t)(b*Hh + h))*Tt + t)*Ss + 2*j;
    double theta = exp(-0.5756462732485115 * (double)j);   // 10000^{-j/16}
    float thf = (float)theta;                               // f32 table value (matches jax)
    double ang = (double)((float)t * thf);                  // f32 angle, exact sincos
    double sn, cs;
    sincos(ang, &sn, &cs);
    float csf = (float)cs, snf = (float)sn;
    float q0 = q[in], q1 = q[in+1];
    rq[out]   = q0*csf - q1*snf;
    rq[out+1] = q1*csf + q0*snf;
    float k0 = k[in], k1 = k[in+1];
    rk[out]   = k0*csf - k1*snf;
    rk[out+1] = k1*csf + k0*snf;
    vt[out]   = v[in];
    vt[out+1] = v[in+1];
}

__global__ __launch_bounds__(256) void attn_scores(const float* __restrict__ Q,
    const float* __restrict__ Kv, float* __restrict__ Sc)
{
    int bh = blockIdx.z;
    int t0 = blockIdx.y * 64;
    int k0 = blockIdx.x * 64;
    if (k0 > t0) return;
    __shared__ float Qs[64][65];
    __shared__ float Ks[64][65];
    const float* Qb = Q  + ((size_t)bh*Tt + t0) * Ss;
    const float* Kb = Kv + ((size_t)bh*Tt + k0) * Ss;
    int tid = threadIdx.x;
    for (int l = tid; l < 64*16; l += 256) {
        int r = l >> 4; int s4 = (l & 15) * 4;
        float4 qv = *(const float4*)(Qb + r*Ss + s4);
        Qs[r][s4] = qv.x; Qs[r][s4+1] = qv.y; Qs[r][s4+2] = qv.z; Qs[r][s4+3] = qv.w;
        float4 kv = *(const float4*)(Kb + r*Ss + s4);
        Ks[r][s4] = kv.x; Ks[r][s4+1] = kv.y; Ks[r][s4+2] = kv.z; Ks[r][s4+3] = kv.w;
    }
    __syncthreads();
    int tx = tid & 15, ty = tid >> 4;
    float acc[4][4];
    #pragma unroll
    for (int i = 0; i < 4; i++)
        #pragma unroll
        for (int j = 0; j < 4; j++) acc[i][j] = 0.f;
    #pragma unroll 4
    for (int s = 0; s < 64; s++) {
        float ar[4], br[4];
        #pragma unroll
        for (int i = 0; i < 4; i++) ar[i] = Qs[ty*4+i][s];
        #pragma unroll
        for (int j = 0; j < 4; j++) br[j] = Ks[tx*4+j][s];
        #pragma unroll
        for (int i = 0; i < 4; i++)
            #pragma unroll
            for (int j = 0; j < 4; j++) acc[i][j] += ar[i]*br[j];
    }
    const float scale = 0.036084391824351615f;
    #pragma unroll
    for (int i = 0; i < 4; i++) {
        size_t off = (size_t)bh*Tt*Tt + (size_t)(t0 + ty*4 + i)*Tt + k0 + tx*4;
        float4 v = make_float4(acc[i][0]*scale, acc[i][1]*scale, acc[i][2]*scale, acc[i][3]*scale);
        *(float4*)&Sc[off] = v;
    }
}

// softmax: exp + reciprocal in DOUBLE (fast-math-proof)
__global__ void softmax_causal(float* __restrict__ Sc)
{
    int row = blockIdx.x;
    int t = row & (Tt - 1);
    float* p = Sc + (size_t)row * Tt;
    int len = t + 1;
    int tid = threadIdx.x;
    __shared__ float sh[8];

    float m = -1e30f;
    for (int k = tid; k < len; k += 256) m = fmaxf(m, p[k]);
    #pragma unroll
    for (int o = 16; o > 0; o >>= 1) m = fmaxf(m, __shfl_xor_sync(0xffffffffu, m, o));
    if ((tid & 31) == 0) sh[tid >> 5] = m;
    __syncthreads();
    m = sh[0];
    #pragma unroll
    for (int w = 1; w < 8; w++) m = fmaxf(m, sh[w]);
    __syncthreads();

    float sum = 0.f;
    for (int k = tid; k < len; k += 256) {
        float e = (float)exp((double)(p[k] - m));
        p[k] = e;
        sum += e;
    }
    #pragma unroll
    for (int o = 16; o > 0; o >>= 1) sum += __shfl_xor_sync(0xffffffffu, sum, o);
    if ((tid & 31) == 0) sh[tid >> 5] = sum;
    __syncthreads();
    sum = 0.f;
    #pragma unroll
    for (int w = 0; w < 8; w++) sum += sh[w];
    float inv = (float)(1.0 / (double)sum);
    for (int k = tid; k < len; k += 256) p[k] *= inv;
    for (int k = len + tid; k < Tt; k += 256) p[k] = 0.f;
}

__global__ __launch_bounds__(256) void attn_av(const float* __restrict__ P,
     const float* __restrict__ V, float* __restrict__ O)
{
    int bh = blockIdx.y;
    int b = bh / Hh, h = bh % Hh;
    int t0 = blockIdx.x * 64;
    __shared__ float Ps[64][17];
    __shared__ float Vs[16][64];
    const float* Pb = P + ((size_t)bh*Tt + t0) * Tt;
    const float* Vb = V + (size_t)bh*Tt*Ss;
    int tid = threadIdx.x;
    int tx = tid & 15, ty = tid >> 4;
    float acc[4][4];
    #pragma unroll
    for (int i = 0; i < 4; i++)
        #pragma unroll
        for (int j = 0; j < 4; j++) acc[i][j] = 0.f;

    int kmax = t0 + 64;
    for (int k0 = 0; k0 < kmax; k0 += 16) {
        __syncthreads();
        {
            int r = tid >> 2; int c4 = (tid & 3) * 4;
            float4 pv = *(const float4*)(Pb + (size_t)r*Tt + k0 + c4);
            Ps[r][c4] = pv.x; Ps[r][c4+1] = pv.y; Ps[r][c4+2] = pv.z; Ps[r][c4+3] = pv.w;
            int r2 = tid >> 4; int c2 = (tid & 15) * 4;
            float4 vv = *(const float4*)(Vb + (size_t)(k0 + r2)*Ss + c2);
            *(float4*)&Vs[r2][c2] = vv;
        }
        __syncthreads();
        #pragma unroll
        for (int k = 0; k < 16; k++) {
            float4 bv = *(const float4*)&Vs[k][tx*4];
            float br[4] = {bv.x, bv.y, bv.z, bv.w};
            float ar[4];
            #pragma unroll
            for (int i = 0; i < 4; i++) ar[i] = Ps[ty*4+i][k];
            #pragma unroll
            for (int i = 0; i < 4; i++)
                #pragma unroll
                for (int j = 0; j < 4; j++) acc[i][j] += ar[i]*br[j];
        }
    }
    #pragma unroll
    for (int i = 0; i < 4; i++) {
        int t = t0 + ty*4 + i;
        size_t o = ((size_t)b*Tt + t)*Cc + h*Ss + tx*4;
        *(float4*)&O[o] = make_float4(acc[i][0], acc[i][1], acc[i][2], acc[i][3]);
    }
}

// SiLU: sigmoid in DOUBLE (fast-math-proof)
__global__ void silu_mul(const float* __restrict__ wx, const float* __restrict__ vx,
                         float* __restrict__ out, int n)
{
    int i = blockIdx.x*256 + threadIdx.x;
    if (i < n) {
        double v = (double)vx[i];
        double sig = 1.0 / (1.0 + exp(-v));
        out[i] = wx[i] * (float)(v * sig);
    }
}

static float* symaddr(const void* sym)
{
    void* p = nullptr;
    cudaGetSymbolAddress(&p, sym);
    return (float*)p;
}

extern "C" void kernel_launch(void* const* d_in, const int* in_sizes, int n_in,
                              void* d_out, int out_size)
{
    const float* x  = (const float*)d_in[0];
    const float* Wq = (const float*)d_in[1];
    const float* Wk = (const float*)d_in[2];
    const float* Wv = (const float*)d_in[3];
    const float* Wo = (const float*)d_in[4];
    const float* g1 = (const float*)d_in[5];
    const float* g2 = (const float*)d_in[6];
    const float* W1 = (const float*)d_in[7];
    const float* b1 = (const float*)d_in[8];
    const float* Ww = (const float*)d_in[9];
    const float* bw = (const float*)d_in[10];
    const float* Wg = (const float*)d_in[11];
    const float* bg = (const float*)d_in[12];
    const float* Wd = (const float*)d_in[13];
    const float* bd = (const float*)d_in[14];
    const float* W2 = (const float*)d_in[15];
    const float* b2 = (const float*)d_in[16];
    float* out = (float*)d_out;

    float* p_h    = symaddr(g_h);
    float* p_q    = symaddr(g_q);
    float* p_k    = symaddr(g_k);
    float* p_v    = symaddr(g_v);
    float* p_rq   = symaddr(g_rq);
    float* p_rk   = symaddr(g_rk);
    float* p_vt   = symaddr(g_vt);
    float* p_sc   = symaddr(g_sc);
    float* p_attn = symaddr(g_attn);
    float* p_out1 = symaddr(g_out1);
    float* p_u    = symaddr(g_u);
    float* p_wx   = symaddr(g_wx);
    float* p_vx   = symaddr(g_vx);
    float* p_ff   = symaddr(g_ff);
    float* p_wp   = symaddr(g_wp);
    float* p_part = symaddr(g_part);
    float* p_scal = symaddr(g_scale);

    const float invn = 1.0f / (float)NTOT;

    sumsq_partial<<<1024, 256>>>(x, NTOT, p_part);
    finalize_scale<<<1, 256>>>(p_part, 1024, invn, p_scal);
    apply_rms<<<NTOT/256, 256>>>(x, p_scal, g1, p_h, NTOT);

    pack_qkv<<<(Hh*Cc*Ss + 255)/256, 256>>>(Wq, Wk, Wv, p_wp);
    sgemm128<false,false><<<dim3(Cc/128, Mm/128), 256>>>(p_h, p_wp,           nullptr, nullptr, p_q, Mm, Cc, Cc);
    sgemm128<false,false><<<dim3(Cc/128, Mm/128), 256>>>(p_h, p_wp + Cc*Cc,   nullptr, nullptr, p_k, Mm, Cc, Cc);
    sgemm128<false,false><<<dim3(Cc/128, Mm/128), 256>>>(p_h, p_wp + 2*Cc*Cc, nullptr, nullptr, p_v, Mm, Cc, Cc);
    rope_reorder<<<(Bb*Tt*Hh*32)/256, 256>>>(p_q, p_k, p_v, p_rq, p_rk, p_vt);

    attn_scores<<<dim3(Tt/64, Tt/64, BHn), 256>>>(p_rq, p_rk, p_sc);
    softmax_causal<<<BHn*Tt, 256>>>(p_sc);
    attn_av<<<dim3(Tt/64, BHn), 256>>>(p_sc, p_vt, p_attn);
    sgemm128<false,true><<<dim3(Cc/128, Mm/128), 256>>>(p_attn, Wo, nullptr, x, p_out1, Mm, Cc, Cc);

    sumsq_partial<<<1024, 256>>>(p_out1, NTOT, p_part);
    finalize_scale<<<1, 256>>>(p_part, 1024, invn, p_scal);
    apply_rms<<<NTOT/256, 256>>>(p_out1, p_scal, g2, p_h, NTOT);

    sgemm128<true,false><<<dim3(FFf/128, Mm/128), 256>>>(p_h,  W1, b1, nullptr, p_u,  Mm, FFf,  Cc);
    sgemm128<true,false><<<dim3(HIDh/128, Mm/128), 256>>>(p_u, Ww, bw, nullptr, p_wx, Mm, HIDh, FFf);
    sgemm128<true,false><<<dim3(HIDh/128, Mm/128), 256>>>(p_u, Wg, bg, nullptr, p_vx, Mm, HIDh, FFf);
    silu_mul<<<(Mm*HIDh)/256, 256>>>(p_wx, p_vx, p_wx, Mm*HIDh);
    sgemm128<true,false><<<dim3(FFf/128, Mm/128), 256>>>(p_wx, Wd, bd, nullptr, p_ff, Mm, FFf, HIDh);
    sgemm128<true,true><<<dim3(Cc/128, Mm/128), 256>>>(p_ff, W2, b2, p_out1, out, Mm, Cc, FFf);
}

// round 14
// speedup vs baseline: 4.4718x; 1.2721x over previous
#include <cuda_runtime.h>
#include <cuda_bf16.h>
#include <math.h>
#include <stdint.h>

#define Bb   4
#define Tt   1024
#define Cc   768
#define Hh   12
#define Ss   64
#define FFf  3072
#define HIDh 2048
#define Mm   (Bb*Tt)
#define NTOT (Mm*Cc)
#define BHn  (Bb*Hh)

__device__ float g_h   [Mm*Cc];
__device__ float g_q   [Mm*Cc];
__device__ float g_k   [Mm*Cc];
__device__ float g_v   [Mm*Cc];
__device__ float g_rq  [Mm*Cc];
__device__ float g_rk  [Mm*Cc];
__device__ float g_vt  [Mm*Cc];
__device__ float g_sc  [(size_t)BHn*Tt*Tt];
__device__ float g_attn[Mm*Cc];
__device__ float g_out1[Mm*Cc];
__device__ float g_u   [Mm*FFf];
__device__ float g_wx  [Mm*HIDh];
__device__ float g_vx  [Mm*HIDh];
__device__ float g_ff  [Mm*FFf];
__device__ float g_wp  [3*Cc*Cc];
__device__ float g_part[1024];
__device__ float g_scale[1];

// ---------------- reductions (unchanged, fast-math-proof) ----------------
__global__ void sumsq_partial(const float* __restrict__ x, int n, float* __restrict__ part)
{
    float s = 0.f;
    for (int i = blockIdx.x*256 + threadIdx.x; i < n; i += gridDim.x*256) {
        float v = x[i]; s += v*v;
    }
    #pragma unroll
    for (int o = 16; o > 0; o >>= 1) s += __shfl_xor_sync(0xffffffffu, s, o);
    __shared__ float sh[8];
    if ((threadIdx.x & 31) == 0) sh[threadIdx.x >> 5] = s;
    __syncthreads();
    if (threadIdx.x == 0) {
        float t = 0.f;
        #pragma unroll
        for (int w = 0; w < 8; w++) t += sh[w];
        part[blockIdx.x] = t;
    }
}

__global__ void finalize_scale(const float* __restrict__ part, int g, float invn, float* __restrict__ scale)
{
    float s = 0.f;
    for (int i = threadIdx.x; i < g; i += 256) s += part[i];
    #pragma unroll
    for (int o = 16; o > 0; o >>= 1) s += __shfl_xor_sync(0xffffffffu, s, o);
    __shared__ float sh[8];
    if ((threadIdx.x & 31) == 0) sh[threadIdx.x >> 5] = s;
    __syncthreads();
    if (threadIdx.x == 0) {
        double t = 0.0;
        for (int w = 0; w < 8; w++) t += (double)sh[w];
        scale[0] = (float)(1.0 / sqrt(1e-6 + t * (double)invn));
    }
}

__global__ void apply_rms(const float* __restrict__ x, const float* __restrict__ scale,
                          const float* __restrict__ g, float* __restrict__ out, int n)
{
    int i = blockIdx.x*256 + threadIdx.x;
    if (i < n) out[i] = x[i] * scale[0] * g[i % Cc];
}

__global__ void pack_qkv(const float* __restrict__ Wq, const float* __restrict__ Wk,
                         const float* __restrict__ Wv, float* __restrict__ Wp)
{
    int i = blockIdx.x*256 + threadIdx.x;
    const int n = Hh*Cc*Ss;
    if (i >= n) return;
    int s = i % Ss; int r = i / Ss; int c = r % Cc; int h = r / Cc;
    int oc = c*Cc + h*Ss + s;
    Wp[oc]       = Wq[i];
    Wp[n + oc]   = Wk[i];
    Wp[2*n + oc] = Wv[i];
}

// ---------------- split-bf16 tensor-core GEMM ----------------
// C = A[MxK] * B[KxN] (+bias)(+res), fp32-accurate via Markidis split:
// acc += Ah*Bh + Ah*Bl + Al*Bh  (dropped Al*Bl ~ 2^-16 relative)
__device__ __forceinline__ void mma16816(float* c, const uint32_t* a, const uint32_t* b)
{
    asm("mma.sync.aligned.m16n8k16.row.col.f32.bf16.bf16.f32 "
        "{%0,%1,%2,%3}, {%4,%5,%6,%7}, {%8,%9}, {%0,%1,%2,%3};"
        : "+f"(c[0]), "+f"(c[1]), "+f"(c[2]), "+f"(c[3])
        : "r"(a[0]), "r"(a[1]), "r"(a[2]), "r"(a[3]), "r"(b[0]), "r"(b[1]));
}

#define SPAD 40   // row stride (bf16 elems) -> conflict-free fragment loads

template<bool BIAS, bool RES>
__global__ __launch_bounds__(256) void hgemm128(
    const float* __restrict__ A, const float* __restrict__ B,
    const float* __restrict__ bias, const float* __restrict__ R,
    float* __restrict__ C, int M, int N, int K)
{
    __shared__ __nv_bfloat16 Ah[128][SPAD];
    __shared__ __nv_bfloat16 Al[128][SPAD];
    __shared__ __nv_bfloat16 Bh[128][SPAD];   // [n][k] transposed
    __shared__ __nv_bfloat16 Bl[128][SPAD];

    const int tid  = threadIdx.x;
    const int lane = tid & 31;
    const int warp = tid >> 5;
    const int wm = (warp >> 2) * 64;    // warp row offset (2 rows of warps)
    const int wn = (warp & 3) * 32;     // warp col offset (4 cols of warps)
    const int bm = blockIdx.y * 128;
    const int bn = blockIdx.x * 128;

    float acc[4][4][4];
    #pragma unroll
    for (int mi = 0; mi < 4; mi++)
        #pragma unroll
        for (int ni = 0; ni < 4; ni++)
            #pragma unroll
            for (int c = 0; c < 4; c++) acc[mi][ni][c] = 0.f;

    const int ar = lane >> 2;          // fragment row within 8
    const int ac = (lane & 3) * 2;     // fragment k within 8 (pair)

    for (int k0 = 0; k0 < K; k0 += 32) {
        // --- load A tile 128x32 (float4) + split ---
        #pragma unroll
        for (int it = 0; it < 4; it++) {
            int l = tid + it*256;                 // 0..1023
            int r = l >> 3, c = (l & 7) * 4;
            float4 v = *(const float4*)&A[(size_t)(bm + r) * K + k0 + c];
            float f[4] = {v.x, v.y, v.z, v.w};
            #pragma unroll
            for (int j = 0; j < 4; j++) {
                __nv_bfloat16 hi = __float2bfloat16_rn(f[j]);
                __nv_bfloat16 lo = __float2bfloat16_rn(f[j] - __bfloat162float(hi));
                Ah[r][c+j] = hi;
                Al[r][c+j] = lo;
            }
        }
        // --- load B tile 32x128 (scalar) + split + transpose to [n][k] ---
        #pragma unroll
        for (int it = 0; it < 16; it++) {
            int l = tid + it*256;                 // 0..4095
            int kk = l >> 7, n = l & 127;
            float v = B[(size_t)(k0 + kk) * N + bn + n];
            __nv_bfloat16 hi = __float2bfloat16_rn(v);
            __nv_bfloat16 lo = __float2bfloat16_rn(v - __bfloat162float(hi));
            Bh[n][kk] = hi;
            Bl[n][kk] = lo;
        }
        __syncthreads();

        #pragma unroll
        for (int ks = 0; ks < 32; ks += 16) {
            uint32_t ah[4][4], al[4][4], bh[4][2], bl[4][2];
            #pragma unroll
            for (int mi = 0; mi < 4; mi++) {
                int row = wm + mi*16;
                ah[mi][0] = *(const uint32_t*)&Ah[row+ar  ][ks+ac  ];
                ah[mi][1] = *(const uint32_t*)&Ah[row+ar+8][ks+ac  ];
                ah[mi][2] = *(const uint32_t*)&Ah[row+ar  ][ks+ac+8];
                ah[mi][3] = *(const uint32_t*)&Ah[row+ar+8][ks+ac+8];
                al[mi][0] = *(const uint32_t*)&Al[row+ar  ][ks+ac  ];
                al[mi][1] = *(const uint32_t*)&Al[row+ar+8][ks+ac  ];
                al[mi][2] = *(const uint32_t*)&Al[row+ar  ][ks+ac+8];
                al[mi][3] = *(const uint32_t*)&Al[row+ar+8][ks+ac+8];
            }
            #pragma unroll
            for (int ni = 0; ni < 4; ni++) {
                int col = wn + ni*8;
                bh[ni][0] = *(const uint32_t*)&Bh[col+ar][ks+ac  ];
                bh[ni][1] = *(const uint32_t*)&Bh[col+ar][ks+ac+8];
                bl[ni][0] = *(const uint32_t*)&Bl[col+ar][ks+ac  ];
                bl[ni][1] = *(const uint32_t*)&Bl[col+ar][ks+ac+8];
            }
            #pragma unroll
            for (int mi = 0; mi < 4; mi++)
                #pragma unroll
                for (int ni = 0; ni < 4; ni++) {
                    mma16816(acc[mi][ni], ah[mi], bh[ni]);
                    mma16816(acc[mi][ni], ah[mi], bl[ni]);
                    mma16816(acc[mi][ni], al[mi], bh[ni]);
                }
        }
        __syncthreads();
    }

    // --- epilogue ---
    #pragma unroll
    for (int mi = 0; mi < 4; mi++) {
        #pragma unroll
        for (int ni = 0; ni < 4; ni++) {
            int row0 = bm + wm + mi*16 + ar;
            int col  = bn + wn + ni*8 + ac;
            #pragma unroll
            for (int half = 0; half < 2; half++) {
                int row = row0 + half*8;
                float2 v = make_float2(acc[mi][ni][half*2], acc[mi][ni][half*2+1]);
                if (BIAS) { v.x += bias[col]; v.y += bias[col+1]; }
                if (RES) {
                    const float2 rr = *(const float2*)&R[(size_t)row*N + col];
                    v.x += rr.x; v.y += rr.y;
                }
                *(float2*)&C[(size_t)row*N + col] = v;
            }
        }
    }
}

// ---------------- RoPE (double sincos, fast-math-proof) ----------------
__global__ void rope_reorder(const float* __restrict__ q, const float* __restrict__ k,
                             const float* __restrict__ v,
                             float* __restrict__ rq, float* __restrict__ rk,
                             float* __restrict__ vt)
{
    int p = blockIdx.x*256 + threadIdx.x;
    if (p >= Bb*Tt*Hh*32) return;
    int j = p & 31;  int r = p >> 5;
    int h = r % Hh;  r /= Hh;
    int t = r % Tt;  int b = r / Tt;
    size_t in  = ((size_t)(b*Tt + t))*Cc + h*Ss + 2*j;
    size_t out = (((size_t)(b*Hh + h))*Tt + t)*Ss + 2*j;
    double theta = exp(-0.5756462732485115 * (double)j);
    float thf = (float)theta;
    double ang = (double)((float)t * thf);
    double sn, cs;
    sincos(ang, &sn, &cs);
    float csf = (float)cs, snf = (float)sn;
    float q0 = q[in], q1 = q[in+1];
    rq[out]   = q0*csf - q1*snf;
    rq[out+1] = q1*csf + q0*snf;
    float k0 = k[in], k1 = k[in+1];
    rk[out]   = k0*csf - k1*snf;
    rk[out+1] = k1*csf + k0*snf;
    vt[out]   = v[in];
    vt[out+1] = v[in+1];
}

__global__ __launch_bounds__(256) void attn_scores(const float* __restrict__ Q,
    const float* __restrict__ Kv, float* __restrict__ Sc)
{
    int bh = blockIdx.z;
    int t0 = blockIdx.y * 64;
    int k0 = blockIdx.x * 64;
    if (k0 > t0) return;
    __shared__ float Qs[64][65];
    __shared__ float Ks[64][65];
    const float* Qb = Q  + ((size_t)bh*Tt + t0) * Ss;
    const float* Kb = Kv + ((size_t)bh*Tt + k0) * Ss;
    int tid = threadIdx.x;
    for (int l = tid; l < 64*16; l += 256) {
        int r = l >> 4; int s4 = (l & 15) * 4;
        float4 qv = *(const float4*)(Qb + r*Ss + s4);
        Qs[r][s4] = qv.x; Qs[r][s4+1] = qv.y; Qs[r][s4+2] = qv.z; Qs[r][s4+3] = qv.w;
        float4 kv = *(const float4*)(Kb + r*Ss + s4);
        Ks[r][s4] = kv.x; Ks[r][s4+1] = kv.y; Ks[r][s4+2] = kv.z; Ks[r][s4+3] = kv.w;
    }
    __syncthreads();
    int tx = tid & 15, ty = tid >> 4;
    float acc[4][4];
    #pragma unroll
    for (int i = 0; i < 4; i++)
        #pragma unroll
        for (int j = 0; j < 4; j++) acc[i][j] = 0.f;
    #pragma unroll 4
    for (int s = 0; s < 64; s++) {
        float ar[4], br[4];
        #pragma unroll
        for (int i = 0; i < 4; i++) ar[i] = Qs[ty*4+i][s];
        #pragma unroll
        for (int j = 0; j < 4; j++) br[j] = Ks[tx*4+j][s];
        #pragma unroll
        for (int i = 0; i < 4; i++)
            #pragma unroll
            for (int j = 0; j < 4; j++) acc[i][j] += ar[i]*br[j];
    }
    const float scale = 0.036084391824351615f;
    #pragma unroll
    for (int i = 0; i < 4; i++) {
        size_t off = (size_t)bh*Tt*Tt + (size_t)(t0 + ty*4 + i)*Tt + k0 + tx*4;
        float4 v = make_float4(acc[i][0]*scale, acc[i][1]*scale, acc[i][2]*scale, acc[i][3]*scale);
        *(float4*)&Sc[off] = v;
    }
}

__global__ void softmax_causal(float* __restrict__ Sc)
{
    int row = blockIdx.x;
    int t = row & (Tt - 1);
    float* p = Sc + (size_t)row * Tt;
    int len = t + 1;
    int tid = threadIdx.x;
    __shared__ float sh[8];

    float m = -1e30f;
    for (int k = tid; k < len; k += 256) m = fmaxf(m, p[k]);
    #pragma unroll
    for (int o = 16; o > 0; o >>= 1) m = fmaxf(m, __shfl_xor_sync(0xffffffffu, m, o));
    if ((tid & 31) == 0) sh[tid >> 5] = m;
    __syncthreads();
    m = sh[0];
    #pragma unroll
    for (int w = 1; w < 8; w++) m = fmaxf(m, sh[w]);
    __syncthreads();

    float sum = 0.f;
    for (int k = tid; k < len; k += 256) {
        float e = (float)exp((double)(p[k] - m));
        p[k] = e;
        sum += e;
    }
    #pragma unroll
    for (int o = 16; o > 0; o >>= 1) sum += __shfl_xor_sync(0xffffffffu, sum, o);
    if ((tid & 31) == 0) sh[tid >> 5] = sum;
    __syncthreads();
    sum = 0.f;
    #pragma unroll
    for (int w = 0; w < 8; w++) sum += sh[w];
    float inv = (float)(1.0 / (double)sum);
    for (int k = tid; k < len; k += 256) p[k] *= inv;
    for (int k = len + tid; k < Tt; k += 256) p[k] = 0.f;
}

__global__ __launch_bounds__(256) void attn_av(const float* __restrict__ P,
     const float* __restrict__ V, float* __restrict__ O)
{
    int bh = blockIdx.y;
    int b = bh / Hh, h = bh % Hh;
    int t0 = blockIdx.x * 64;
    __shared__ float Ps[64][17];
    __shared__ float Vs[16][64];
    const float* Pb = P + ((size_t)bh*Tt + t0) * Tt;
    const float* Vb = V + (size_t)bh*Tt*Ss;
    int tid = threadIdx.x;
    int tx = tid & 15, ty = tid >> 4;
    float acc[4][4];
    #pragma unroll
    for (int i = 0; i < 4; i++)
        #pragma unroll
        for (int j = 0; j < 4; j++) acc[i][j] = 0.f;

    int kmax = t0 + 64;
    for (int k0 = 0; k0 < kmax; k0 += 16) {
        __syncthreads();
        {
            int r = tid >> 2; int c4 = (tid & 3) * 4;
            float4 pv = *(const float4*)(Pb + (size_t)r*Tt + k0 + c4);
            Ps[r][c4] = pv.x; Ps[r][c4+1] = pv.y; Ps[r][c4+2] = pv.z; Ps[r][c4+3] = pv.w;
            int r2 = tid >> 4; int c2 = (tid & 15) * 4;
            float4 vv = *(const float4*)(Vb + (size_t)(k0 + r2)*Ss + c2);
            *(float4*)&Vs[r2][c2] = vv;
        }
        __syncthreads();
        #pragma unroll
        for (int k = 0; k < 16; k++) {
            float4 bv = *(const float4*)&Vs[k][tx*4];
            float br[4] = {bv.x, bv.y, bv.z, bv.w};
            float ar[4];
            #pragma unroll
            for (int i = 0; i < 4; i++) ar[i] = Ps[ty*4+i][k];
            #pragma unroll
            for (int i = 0; i < 4; i++)
                #pragma unroll
                for (int j = 0; j < 4; j++) acc[i][j] += ar[i]*br[j];
        }
    }
    #pragma unroll
    for (int i = 0; i < 4; i++) {
        int t = t0 + ty*4 + i;
        size_t o = ((size_t)b*Tt + t)*Cc + h*Ss + tx*4;
        *(float4*)&O[o] = make_float4(acc[i][0], acc[i][1], acc[i][2], acc[i][3]);
    }
}

__global__ void silu_mul(const float* __restrict__ wx, const float* __restrict__ vx,
                         float* __restrict__ out, int n)
{
    int i = blockIdx.x*256 + threadIdx.x;
    if (i < n) {
        double v = (double)vx[i];
        double sig = 1.0 / (1.0 + exp(-v));
        out[i] = wx[i] * (float)(v * sig);
    }
}

static float* symaddr(const void* sym)
{
    void* p = nullptr;
    cudaGetSymbolAddress(&p, sym);
    return (float*)p;
}

extern "C" void kernel_launch(void* const* d_in, const int* in_sizes, int n_in,
                              void* d_out, int out_size)
{
    const float* x  = (const float*)d_in[0];
    const float* Wq = (const float*)d_in[1];
    const float* Wk = (const float*)d_in[2];
    const float* Wv = (const float*)d_in[3];
    const float* Wo = (const float*)d_in[4];
    const float* g1 = (const float*)d_in[5];
    const float* g2 = (const float*)d_in[6];
    const float* W1 = (const float*)d_in[7];
    const float* b1 = (const float*)d_in[8];
    const float* Ww = (const float*)d_in[9];
    const float* bw = (const float*)d_in[10];
    const float* Wg = (const float*)d_in[11];
    const float* bg = (const float*)d_in[12];
    const float* Wd = (const float*)d_in[13];
    const float* bd = (const float*)d_in[14];
    const float* W2 = (const float*)d_in[15];
    const float* b2 = (const float*)d_in[16];
    float* out = (float*)d_out;

    float* p_h    = symaddr(g_h);
    float* p_q    = symaddr(g_q);
    float* p_k    = symaddr(g_k);
    float* p_v    = symaddr(g_v);
    float* p_rq   = symaddr(g_rq);
    float* p_rk   = symaddr(g_rk);
    float* p_vt   = symaddr(g_vt);
    float* p_sc   = symaddr(g_sc);
    float* p_attn = symaddr(g_attn);
    float* p_out1 = symaddr(g_out1);
    float* p_u    = symaddr(g_u);
    float* p_wx   = symaddr(g_wx);
    float* p_vx   = symaddr(g_vx);
    float* p_ff   = symaddr(g_ff);
    float* p_wp   = symaddr(g_wp);
    float* p_part = symaddr(g_part);
    float* p_scal = symaddr(g_scale);

    const float invn = 1.0f / (float)NTOT;

    sumsq_partial<<<1024, 256>>>(x, NTOT, p_part);
    finalize_scale<<<1, 256>>>(p_part, 1024, invn, p_scal);
    apply_rms<<<NTOT/256, 256>>>(x, p_scal, g1, p_h, NTOT);

    pack_qkv<<<(Hh*Cc*Ss + 255)/256, 256>>>(Wq, Wk, Wv, p_wp);
    hgemm128<false,false><<<dim3(Cc/128, Mm/128), 256>>>(p_h, p_wp,           nullptr, nullptr, p_q, Mm, Cc, Cc);
    hgemm128<false,false><<<dim3(Cc/128, Mm/128), 256>>>(p_h, p_wp + Cc*Cc,   nullptr, nullptr, p_k, Mm, Cc, Cc);
    hgemm128<false,false><<<dim3(Cc/128, Mm/128), 256>>>(p_h, p_wp + 2*Cc*Cc, nullptr, nullptr, p_v, Mm, Cc, Cc);
    rope_reorder<<<(Bb*Tt*Hh*32)/256, 256>>>(p_q, p_k, p_v, p_rq, p_rk, p_vt);

    attn_scores<<<dim3(Tt/64, Tt/64, BHn), 256>>>(p_rq, p_rk, p_sc);
    softmax_causal<<<BHn*Tt, 256>>>(p_sc);
    attn_av<<<dim3(Tt/64, BHn), 256>>>(p_sc, p_vt, p_attn);
    hgemm128<false,true><<<dim3(Cc/128, Mm/128), 256>>>(p_attn, Wo, nullptr, x, p_out1, Mm, Cc, Cc);

    sumsq_partial<<<1024, 256>>>(p_out1, NTOT, p_part);
    finalize_scale<<<1, 256>>>(p_part, 1024, invn, p_scal);
    apply_rms<<<NTOT/256, 256>>>(p_out1, p_scal, g2, p_h, NTOT);

    hgemm128<true,false><<<dim3(FFf/128, Mm/128), 256>>>(p_h,  W1, b1, nullptr, p_u,  Mm, FFf,  Cc);
    hgemm128<true,false><<<dim3(HIDh/128, Mm/128), 256>>>(p_u, Ww, bw, nullptr, p_wx, Mm, HIDh, FFf);
    hgemm128<true,false><<<dim3(HIDh/128, Mm/128), 256>>>(p_u, Wg, bg, nullptr, p_vx, Mm, HIDh, FFf);
    silu_mul<<<(Mm*HIDh)/256, 256>>>(p_wx, p_vx, p_wx, Mm*HIDh);
    hgemm128<true,false><<<dim3(FFf/128, Mm/128), 256>>>(p_wx, Wd, bd, nullptr, p_ff, Mm, FFf, HIDh);
    hgemm128<true,true><<<dim3(Cc/128, Mm/128), 256>>>(p_ff, W2, b2, p_out1, out, Mm, Cc, FFf);
}

// round 15
// speedup vs baseline: 9.3924x; 2.1004x over previous
#include <cuda_runtime.h>
#include <cuda_bf16.h>
#include <math.h>
#include <stdint.h>

#define Bb   4
#define Tt   1024
#define Cc   768
#define Hh   12
#define Ss   64
#define FFf  3072
#define HIDh 2048
#define Mm   (Bb*Tt)
#define NTOT (Mm*Cc)
#define BHn  (Bb*Hh)

__device__ float g_h   [Mm*Cc];
__device__ float g_q   [Mm*Cc];
__device__ float g_k   [Mm*Cc];
__device__ float g_v   [Mm*Cc];
__device__ float g_rq  [Mm*Cc];
__device__ float g_rk  [Mm*Cc];
__device__ float g_vt  [Mm*Cc];
__device__ float g_sc  [(size_t)BHn*Tt*Tt];
__device__ float g_attn[Mm*Cc];
__device__ float g_out1[Mm*Cc];
__device__ float g_u   [Mm*FFf];
__device__ float g_wx  [Mm*HIDh];
__device__ float g_vx  [Mm*HIDh];
__device__ float g_ff  [Mm*FFf];
__device__ float g_wp  [3*Cc*Cc];
__device__ float g_part[1024];
__device__ float g_scale[1];

__device__ __forceinline__ float tf32r(float x)
{
    uint32_t u;
    asm("cvt.rna.tf32.f32 %0, %1;" : "=r"(u) : "f"(x));
    return __uint_as_float(u);
}

// ---------------- reductions ----------------
__global__ void sumsq_partial(const float* __restrict__ x, int n, float* __restrict__ part)
{
    float s = 0.f;
    for (int i = blockIdx.x*256 + threadIdx.x; i < n; i += gridDim.x*256) {
        float v = x[i]; s += v*v;
    }
    #pragma unroll
    for (int o = 16; o > 0; o >>= 1) s += __shfl_xor_sync(0xffffffffu, s, o);
    __shared__ float sh[8];
    if ((threadIdx.x & 31) == 0) sh[threadIdx.x >> 5] = s;
    __syncthreads();
    if (threadIdx.x == 0) {
        float t = 0.f;
        #pragma unroll
        for (int w = 0; w < 8; w++) t += sh[w];
        part[blockIdx.x] = t;
    }
}

__global__ void finalize_scale(const float* __restrict__ part, int g, float invn, float* __restrict__ scale)
{
    float s = 0.f;
    for (int i = threadIdx.x; i < g; i += 256) s += part[i];
    #pragma unroll
    for (int o = 16; o > 0; o >>= 1) s += __shfl_xor_sync(0xffffffffu, s, o);
    __shared__ float sh[8];
    if ((threadIdx.x & 31) == 0) sh[threadIdx.x >> 5] = s;
    __syncthreads();
    if (threadIdx.x == 0) {
        double t = 0.0;
        for (int w = 0; w < 8; w++) t += (double)sh[w];
        scale[0] = (float)(1.0 / sqrt(1e-6 + t * (double)invn));
    }
}

__global__ void apply_rms(const float* __restrict__ x, const float* __restrict__ scale,
                          const float* __restrict__ g, float* __restrict__ out, int n)
{
    int i = blockIdx.x*256 + threadIdx.x;
    if (i < n) out[i] = x[i] * scale[0] * g[i % Cc];
}

__global__ void pack_qkv(const float* __restrict__ Wq, const float* __restrict__ Wk,
                         const float* __restrict__ Wv, float* __restrict__ Wp)
{
    int i = blockIdx.x*256 + threadIdx.x;
    const int n = Hh*Cc*Ss;
    if (i >= n) return;
    int s = i % Ss; int r = i / Ss; int c = r % Cc; int h = r / Cc;
    int oc = c*Cc + h*Ss + s;
    Wp[oc]       = Wq[i];
    Wp[n + oc]   = Wk[i];
    Wp[2*n + oc] = Wv[i];
}

// ---------------- tf32 tensor-core GEMM ----------------
// C = A[MxK]*B[KxN] (+bias)(+res); inputs tf32-rounded (measured output noise 1.5e-4)
__device__ __forceinline__ void mma1688(float* c, const uint32_t* a, const uint32_t* b)
{
    asm("mma.sync.aligned.m16n8k8.row.col.f32.tf32.tf32.f32 "
        "{%0,%1,%2,%3}, {%4,%5,%6,%7}, {%8,%9}, {%0,%1,%2,%3};"
        : "+f"(c[0]), "+f"(c[1]), "+f"(c[2]), "+f"(c[3])
        : "r"(a[0]), "r"(a[1]), "r"(a[2]), "r"(a[3]), "r"(b[0]), "r"(b[1]));
}

#define ASTR 36    // A smem row stride: bank = 4r+k, conflict-free
#define BSTR 136   // B smem row stride: bank = 8k+n, conflict-free

template<bool BIAS, bool RES>
__global__ __launch_bounds__(256) void tgemm128(
    const float* __restrict__ A, const float* __restrict__ B,
    const float* __restrict__ bias, const float* __restrict__ R,
    float* __restrict__ C, int M, int N, int K)
{
    __shared__ float As[128][ASTR];   // [m][k]
    __shared__ float Bs[32][BSTR];    // [k][n]

    const int tid  = threadIdx.x;
    const int lane = tid & 31;
    const int warp = tid >> 5;
    const int wm = (warp >> 2) * 64;
    const int wn = (warp & 3) * 32;
    const int bm = blockIdx.y * 128;
    const int bn = blockIdx.x * 128;

    const int qr = lane >> 2;      // 0..7
    const int qk = lane & 3;       // 0..3

    float acc[4][4][4];
    #pragma unroll
    for (int mi = 0; mi < 4; mi++)
        #pragma unroll
        for (int ni = 0; ni < 4; ni++)
            #pragma unroll
            for (int c = 0; c < 4; c++) acc[mi][ni][c] = 0.f;

    // prefetch first tile into registers
    float4 aReg[4], bReg[4];
    #pragma unroll
    for (int it = 0; it < 4; it++) {
        int l = tid + it*256;
        int r = l >> 3, c = (l & 7) * 4;
        aReg[it] = *(const float4*)&A[(size_t)(bm + r) * K + c];
        int kk = l >> 5, n = (l & 31) * 4;
        bReg[it] = *(const float4*)&B[(size_t)kk * N + bn + n];
    }

    for (int k0 = 0; k0 < K; k0 += 32) {
        // store regs -> smem (with tf32 rounding)
        #pragma unroll
        for (int it = 0; it < 4; it++) {
            int l = tid + it*256;
            int r = l >> 3, c = (l & 7) * 4;
            As[r][c]   = tf32r(aReg[it].x);
            As[r][c+1] = tf32r(aReg[it].y);
            As[r][c+2] = tf32r(aReg[it].z);
            As[r][c+3] = tf32r(aReg[it].w);
            int kk = l >> 5, n = (l & 31) * 4;
            Bs[kk][n]   = tf32r(bReg[it].x);
            Bs[kk][n+1] = tf32r(bReg[it].y);
            Bs[kk][n+2] = tf32r(bReg[it].z);
            Bs[kk][n+3] = tf32r(bReg[it].w);
        }
        __syncthreads();

        // prefetch next tile while computing
        if (k0 + 32 < K) {
            #pragma unroll
            for (int it = 0; it < 4; it++) {
                int l = tid + it*256;
                int r = l >> 3, c = (l & 7) * 4;
                aReg[it] = *(const float4*)&A[(size_t)(bm + r) * K + k0 + 32 + c];
                int kk = l >> 5, n = (l & 31) * 4;
                bReg[it] = *(const float4*)&B[(size_t)(k0 + 32 + kk) * N + bn + n];
            }
        }

        #pragma unroll
        for (int ks = 0; ks < 32; ks += 8) {
            uint32_t af[4][4], bf[4][2];
            #pragma unroll
            for (int mi = 0; mi < 4; mi++) {
                int row = wm + mi*16 + qr;
                af[mi][0] = __float_as_uint(As[row  ][ks + qk]);
                af[mi][1] = __float_as_uint(As[row+8][ks + qk]);
                af[mi][2] = __float_as_uint(As[row  ][ks + qk + 4]);
                af[mi][3] = __float_as_uint(As[row+8][ks + qk + 4]);
            }
            #pragma unroll
            for (int ni = 0; ni < 4; ni++) {
                int col = wn + ni*8 + qr;
                bf[ni][0] = __float_as_uint(Bs[ks + qk    ][col]);
                bf[ni][1] = __float_as_uint(Bs[ks + qk + 4][col]);
            }
            #pragma unroll
            for (int mi = 0; mi < 4; mi++)
                #pragma unroll
                for (int ni = 0; ni < 4; ni++)
                    mma1688(acc[mi][ni], af[mi], bf[ni]);
        }
        __syncthreads();
    }

    #pragma unroll
    for (int mi = 0; mi < 4; mi++) {
        #pragma unroll
        for (int ni = 0; ni < 4; ni++) {
            int row0 = bm + wm + mi*16 + qr;
            int col  = bn + wn + ni*8 + qk*2;
            #pragma unroll
            for (int half = 0; half < 2; half++) {
                int row = row0 + half*8;
                float2 v = make_float2(acc[mi][ni][half*2], acc[mi][ni][half*2+1]);
                if (BIAS) { v.x += bias[col]; v.y += bias[col+1]; }
                if (RES) {
                    const float2 rr = *(const float2*)&R[(size_t)row*N + col];
                    v.x += rr.x; v.y += rr.y;
                }
                *(float2*)&C[(size_t)row*N + col] = v;
            }
        }
    }
}

// ---------------- RoPE (double sincos, fast-math-proof) ----------------
__global__ void rope_reorder(const float* __restrict__ q, const float* __restrict__ k,
                             const float* __restrict__ v,
                             float* __restrict__ rq, float* __restrict__ rk,
                             float* __restrict__ vt)
{
    int p = blockIdx.x*256 + threadIdx.x;
    if (p >= Bb*Tt*Hh*32) return;
    int j = p & 31;  int r = p >> 5;
    int h = r % Hh;  r /= Hh;
    int t = r % Tt;  int b = r / Tt;
    size_t in  = ((size_t)(b*Tt + t))*Cc + h*Ss + 2*j;
    size_t out = (((size_t)(b*Hh + h))*Tt + t)*Ss + 2*j;
    double theta = exp(-0.5756462732485115 * (double)j);
    float thf = (float)theta;
    double ang = (double)((float)t * thf);
    double sn, cs;
    sincos(ang, &sn, &cs);
    float csf = (float)cs, snf = (float)sn;
    float q0 = q[in], q1 = q[in+1];
    rq[out]   = q0*csf - q1*snf;
    rq[out+1] = q1*csf + q0*snf;
    float k0 = k[in], k1 = k[in+1];
    rk[out]   = k0*csf - k1*snf;
    rk[out+1] = k1*csf + k0*snf;
    vt[out]   = v[in];
    vt[out+1] = v[in+1];
}

__global__ __launch_bounds__(256) void attn_scores(const float* __restrict__ Q,
    const float* __restrict__ Kv, float* __restrict__ Sc)
{
    int bh = blockIdx.z;
    int t0 = blockIdx.y * 64;
    int k0 = blockIdx.x * 64;
    if (k0 > t0) return;
    __shared__ float Qs[64][65];
    __shared__ float Ks[64][65];
    const float* Qb = Q  + ((size_t)bh*Tt + t0) * Ss;
    const float* Kb = Kv + ((size_t)bh*Tt + k0) * Ss;
    int tid = threadIdx.x;
    for (int l = tid; l < 64*16; l += 256) {
        int r = l >> 4; int s4 = (l & 15) * 4;
        float4 qv = *(const float4*)(Qb + r*Ss + s4);
        Qs[r][s4] = qv.x; Qs[r][s4+1] = qv.y; Qs[r][s4+2] = qv.z; Qs[r][s4+3] = qv.w;
        float4 kv = *(const float4*)(Kb + r*Ss + s4);
        Ks[r][s4] = kv.x; Ks[r][s4+1] = kv.y; Ks[r][s4+2] = kv.z; Ks[r][s4+3] = kv.w;
    }
    __syncthreads();
    int tx = tid & 15, ty = tid >> 4;
    float acc[4][4];
    #pragma unroll
    for (int i = 0; i < 4; i++)
        #pragma unroll
        for (int j = 0; j < 4; j++) acc[i][j] = 0.f;
    #pragma unroll 4
    for (int s = 0; s < 64; s++) {
        float ar[4], br[4];
        #pragma unroll
        for (int i = 0; i < 4; i++) ar[i] = Qs[ty*4+i][s];
        #pragma unroll
        for (int j = 0; j < 4; j++) br[j] = Ks[tx*4+j][s];
        #pragma unroll
        for (int i = 0; i < 4; i++)
            #pragma unroll
            for (int j = 0; j < 4; j++) acc[i][j] += ar[i]*br[j];
    }
    const float scale = 0.036084391824351615f;
    #pragma unroll
    for (int i = 0; i < 4; i++) {
        size_t off = (size_t)bh*Tt*Tt + (size_t)(t0 + ty*4 + i)*Tt + k0 + tx*4;
        float4 v = make_float4(acc[i][0]*scale, acc[i][1]*scale, acc[i][2]*scale, acc[i][3]*scale);
        *(float4*)&Sc[off] = v;
    }
}

__global__ void softmax_causal(float* __restrict__ Sc)
{
    int row = blockIdx.x;
    int t = row & (Tt - 1);
    float* p = Sc + (size_t)row * Tt;
    int len = t + 1;
    int tid = threadIdx.x;
    __shared__ float sh[8];

    float m = -1e30f;
    for (int k = tid; k < len; k += 256) m = fmaxf(m, p[k]);
    #pragma unroll
    for (int o = 16; o > 0; o >>= 1) m = fmaxf(m, __shfl_xor_sync(0xffffffffu, m, o));
    if ((tid & 31) == 0) sh[tid >> 5] = m;
    __syncthreads();
    m = sh[0];
    #pragma unroll
    for (int w = 1; w < 8; w++) m = fmaxf(m, sh[w]);
    __syncthreads();

    float sum = 0.f;
    for (int k = tid; k < len; k += 256) {
        float e = (float)exp((double)(p[k] - m));
        p[k] = e;
        sum += e;
    }
    #pragma unroll
    for (int o = 16; o > 0; o >>= 1) sum += __shfl_xor_sync(0xffffffffu, sum, o);
    if ((tid & 31) == 0) sh[tid >> 5] = sum;
    __syncthreads();
    sum = 0.f;
    #pragma unroll
    for (int w = 0; w < 8; w++) sum += sh[w];
    float inv = (float)(1.0 / (double)sum);
    for (int k = tid; k < len; k += 256) p[k] *= inv;
    for (int k = len + tid; k < Tt; k += 256) p[k] = 0.f;
}

__global__ __launch_bounds__(256) void attn_av(const float* __restrict__ P,
     const float* __restrict__ V, float* __restrict__ O)
{
    int bh = blockIdx.y;
    int b = bh / Hh, h = bh % Hh;
    int t0 = blockIdx.x * 64;
    __shared__ float Ps[64][17];
    __shared__ float Vs[16][64];
    const float* Pb = P + ((size_t)bh*Tt + t0) * Tt;
    const float* Vb = V + (size_t)bh*Tt*Ss;
    int tid = threadIdx.x;
    int tx = tid & 15, ty = tid >> 4;
    float acc[4][4];
    #pragma unroll
    for (int i = 0; i < 4; i++)
        #pragma unroll
        for (int j = 0; j < 4; j++) acc[i][j] = 0.f;

    int kmax = t0 + 64;
    for (int k0 = 0; k0 < kmax; k0 += 16) {
        __syncthreads();
        {
            int r = tid >> 2; int c4 = (tid & 3) * 4;
            float4 pv = *(const float4*)(Pb + (size_t)r*Tt + k0 + c4);
            Ps[r][c4] = pv.x; Ps[r][c4+1] = pv.y; Ps[r][c4+2] = pv.z; Ps[r][c4+3] = pv.w;
            int r2 = tid >> 4; int c2 = (tid & 15) * 4;
            float4 vv = *(const float4*)(Vb + (size_t)(k0 + r2)*Ss + c2);
            *(float4*)&Vs[r2][c2] = vv;
        }
        __syncthreads();
        #pragma unroll
        for (int k = 0; k < 16; k++) {
            float4 bv = *(const float4*)&Vs[k][tx*4];
            float br[4] = {bv.x, bv.y, bv.z, bv.w};
            float ar[4];
            #pragma unroll
            for (int i = 0; i < 4; i++) ar[i] = Ps[ty*4+i][k];
            #pragma unroll
            for (int i = 0; i < 4; i++)
                #pragma unroll
                for (int j = 0; j < 4; j++) acc[i][j] += ar[i]*br[j];
        }
    }
    #pragma unroll
    for (int i = 0; i < 4; i++) {
        int t = t0 + ty*4 + i;
        size_t o = ((size_t)b*Tt + t)*Cc + h*Ss + tx*4;
        *(float4*)&O[o] = make_float4(acc[i][0], acc[i][1], acc[i][2], acc[i][3]);
    }
}

__global__ void silu_mul(const float* __restrict__ wx, const float* __restrict__ vx,
                         float* __restrict__ out, int n)
{
    int i = blockIdx.x*256 + threadIdx.x;
    if (i < n) {
        double v = (double)vx[i];
        double sig = 1.0 / (1.0 + exp(-v));
        out[i] = wx[i] * (float)(v * sig);
    }
}

static float* symaddr(const void* sym)
{
    void* p = nullptr;
    cudaGetSymbolAddress(&p, sym);
    return (float*)p;
}

extern "C" void kernel_launch(void* const* d_in, const int* in_sizes, int n_in,
                              void* d_out, int out_size)
{
    const float* x  = (const float*)d_in[0];
    const float* Wq = (const float*)d_in[1];
    const float* Wk = (const float*)d_in[2];
    const float* Wv = (const float*)d_in[3];
    const float* Wo = (const float*)d_in[4];
    const float* g1 = (const float*)d_in[5];
    const float* g2 = (const float*)d_in[6];
    const float* W1 = (const float*)d_in[7];
    const float* b1 = (const float*)d_in[8];
    const float* Ww = (const float*)d_in[9];
    const float* bw = (const float*)d_in[10];
    const float* Wg = (const float*)d_in[11];
    const float* bg = (const float*)d_in[12];
    const float* Wd = (const float*)d_in[13];
    const float* bd = (const float*)d_in[14];
    const float* W2 = (const float*)d_in[15];
    const float* b2 = (const float*)d_in[16];
    float* out = (float*)d_out;

    float* p_h    = symaddr(g_h);
    float* p_q    = symaddr(g_q);
    float* p_k    = symaddr(g_k);
    float* p_v    = symaddr(g_v);
    float* p_rq   = symaddr(g_rq);
    float* p_rk   = symaddr(g_rk);
    float* p_vt   = symaddr(g_vt);
    float* p_sc   = symaddr(g_sc);
    float* p_attn = symaddr(g_attn);
    float* p_out1 = symaddr(g_out1);
    float* p_u    = symaddr(g_u);
    float* p_wx   = symaddr(g_wx);
    float* p_vx   = symaddr(g_vx);
    float* p_ff   = symaddr(g_ff);
    float* p_wp   = symaddr(g_wp);
    float* p_part = symaddr(g_part);
    float* p_scal = symaddr(g_scale);

    const float invn = 1.0f / (float)NTOT;

    sumsq_partial<<<1024, 256>>>(x, NTOT, p_part);
    finalize_scale<<<1, 256>>>(p_part, 1024, invn, p_scal);
    apply_rms<<<NTOT/256, 256>>>(x, p_scal, g1, p_h, NTOT);

    pack_qkv<<<(Hh*Cc*Ss + 255)/256, 256>>>(Wq, Wk, Wv, p_wp);
    tgemm128<false,false><<<dim3(Cc/128, Mm/128), 256>>>(p_h, p_wp,           nullptr, nullptr, p_q, Mm, Cc, Cc);
    tgemm128<false,false><<<dim3(Cc/128, Mm/128), 256>>>(p_h, p_wp + Cc*Cc,   nullptr, nullptr, p_k, Mm, Cc, Cc);
    tgemm128<false,false><<<dim3(Cc/128, Mm/128), 256>>>(p_h, p_wp + 2*Cc*Cc, nullptr, nullptr, p_v, Mm, Cc, Cc);
    rope_reorder<<<(Bb*Tt*Hh*32)/256, 256>>>(p_q, p_k, p_v, p_rq, p_rk, p_vt);

    attn_scores<<<dim3(Tt/64, Tt/64, BHn), 256>>>(p_rq, p_rk, p_sc);
    softmax_causal<<<BHn*Tt, 256>>>(p_sc);
    attn_av<<<dim3(Tt/64, BHn), 256>>>(p_sc, p_vt, p_attn);
    tgemm128<false,true><<<dim3(Cc/128, Mm/128), 256>>>(p_attn, Wo, nullptr, x, p_out1, Mm, Cc, Cc);

    sumsq_partial<<<1024, 256>>>(p_out1, NTOT, p_part);
    finalize_scale<<<1, 256>>>(p_part, 1024, invn, p_scal);
    apply_rms<<<NTOT/256, 256>>>(p_out1, p_scal, g2, p_h, NTOT);

    tgemm128<true,false><<<dim3(FFf/128, Mm/128), 256>>>(p_h,  W1, b1, nullptr, p_u,  Mm, FFf,  Cc);
    tgemm128<true,false><<<dim3(HIDh/128, Mm/128), 256>>>(p_u, Ww, bw, nullptr, p_wx, Mm, HIDh, FFf);
    tgemm128<true,false><<<dim3(HIDh/128, Mm/128), 256>>>(p_u, Wg, bg, nullptr, p_vx, Mm, HIDh, FFf);
    silu_mul<<<(Mm*HIDh)/256, 256>>>(p_wx, p_vx, p_wx, Mm*HIDh);
    tgemm128<true,false><<<dim3(FFf/128, Mm/128), 256>>>(p_wx, Wd, bd, nullptr, p_ff, Mm, FFf, HIDh);
    tgemm128<true,true><<<dim3(Cc/128, Mm/128), 256>>>(p_ff, W2, b2, p_out1, out, Mm, Cc, FFf);
}

// round 16
// speedup vs baseline: 11.0603x; 1.1776x over previous
#include <cuda_runtime.h>
#include <cuda_bf16.h>
#include <math.h>
#include <stdint.h>

#define Bb   4
#define Tt   1024
#define Cc   768
#define Hh   12
#define Ss   64
#define FFf  3072
#define HIDh 2048
#define Mm   (Bb*Tt)
#define NTOT (Mm*Cc)
#define BHn  (Bb*Hh)

__device__ float g_h   [Mm*Cc];
__device__ float g_q   [Mm*Cc];
__device__ float g_k   [Mm*Cc];
__device__ float g_v   [Mm*Cc];
__device__ float g_rq  [Mm*Cc];
__device__ float g_rk  [Mm*Cc];
__device__ float g_vt  [Mm*Cc];
__device__ float g_attn[Mm*Cc];
__device__ float g_out1[Mm*Cc];
__device__ float g_u   [Mm*FFf];
__device__ float g_wx  [Mm*HIDh];
__device__ float g_vx  [Mm*HIDh];
__device__ float g_ff  [Mm*FFf];
__device__ float g_wp  [3*Cc*Cc];
__device__ float g_part[1024];
__device__ float g_scale[1];

__device__ __forceinline__ float tf32r(float x)
{
    uint32_t u;
    asm("cvt.rna.tf32.f32 %0, %1;" : "=r"(u) : "f"(x));
    return __uint_as_float(u);
}

__device__ __forceinline__ void mma1688(float* c, const uint32_t* a, const uint32_t* b)
{
    asm("mma.sync.aligned.m16n8k8.row.col.f32.tf32.tf32.f32 "
        "{%0,%1,%2,%3}, {%4,%5,%6,%7}, {%8,%9}, {%0,%1,%2,%3};"
        : "+f"(c[0]), "+f"(c[1]), "+f"(c[2]), "+f"(c[3])
        : "r"(a[0]), "r"(a[1]), "r"(a[2]), "r"(a[3]), "r"(b[0]), "r"(b[1]));
}

// ---------------- reductions ----------------
__global__ void sumsq_partial(const float* __restrict__ x, int n, float* __restrict__ part)
{
    float s = 0.f;
    for (int i = blockIdx.x*256 + threadIdx.x; i < n; i += gridDim.x*256) {
        float v = x[i]; s += v*v;
    }
    #pragma unroll
    for (int o = 16; o > 0; o >>= 1) s += __shfl_xor_sync(0xffffffffu, s, o);
    __shared__ float sh[8];
    if ((threadIdx.x & 31) == 0) sh[threadIdx.x >> 5] = s;
    __syncthreads();
    if (threadIdx.x == 0) {
        float t = 0.f;
        #pragma unroll
        for (int w = 0; w < 8; w++) t += sh[w];
        part[blockIdx.x] = t;
    }
}

__global__ void finalize_scale(const float* __restrict__ part, int g, float invn, float* __restrict__ scale)
{
    float s = 0.f;
    for (int i = threadIdx.x; i < g; i += 256) s += part[i];
    #pragma unroll
    for (int o = 16; o > 0; o >>= 1) s += __shfl_xor_sync(0xffffffffu, s, o);
    __shared__ float sh[8];
    if ((threadIdx.x & 31) == 0) sh[threadIdx.x >> 5] = s;
    __syncthreads();
    if (threadIdx.x == 0) {
        double t = 0.0;
        for (int w = 0; w < 8; w++) t += (double)sh[w];
        scale[0] = (float)(1.0 / sqrt(1e-6 + t * (double)invn));
    }
}

__global__ void apply_rms(const float* __restrict__ x, const float* __restrict__ scale,
                          const float* __restrict__ g, float* __restrict__ out, int n)
{
    int i = blockIdx.x*256 + threadIdx.x;
    if (i < n) out[i] = x[i] * scale[0] * g[i % Cc];
}

__global__ void pack_qkv(const float* __restrict__ Wq, const float* __restrict__ Wk,
                         const float* __restrict__ Wv, float* __restrict__ Wp)
{
    int i = blockIdx.x*256 + threadIdx.x;
    const int n = Hh*Cc*Ss;
    if (i >= n) return;
    int s = i % Ss; int r = i / Ss; int c = r % Cc; int h = r / Cc;
    int oc = c*Cc + h*Ss + s;
    Wp[oc]       = Wq[i];
    Wp[n + oc]   = Wk[i];
    Wp[2*n + oc] = Wv[i];
}

// ---------------- tf32 GEMM (R15, unchanged) ----------------
#define ASTR 36
#define BSTR 136

template<bool BIAS, bool RES>
__global__ __launch_bounds__(256) void tgemm128(
    const float* __restrict__ A, const float* __restrict__ B,
    const float* __restrict__ bias, const float* __restrict__ R,
    float* __restrict__ C, int M, int N, int K)
{
    __shared__ float As[128][ASTR];
    __shared__ float Bs[32][BSTR];

    const int tid  = threadIdx.x;
    const int lane = tid & 31;
    const int warp = tid >> 5;
    const int wm = (warp >> 2) * 64;
    const int wn = (warp & 3) * 32;
    const int bm = blockIdx.y * 128;
    const int bn = blockIdx.x * 128;
    const int qr = lane >> 2;
    const int qk = lane & 3;

    float acc[4][4][4];
    #pragma unroll
    for (int mi = 0; mi < 4; mi++)
        #pragma unroll
        for (int ni = 0; ni < 4; ni++)
            #pragma unroll
            for (int c = 0; c < 4; c++) acc[mi][ni][c] = 0.f;

    float4 aReg[4], bReg[4];
    #pragma unroll
    for (int it = 0; it < 4; it++) {
        int l = tid + it*256;
        int r = l >> 3, c = (l & 7) * 4;
        aReg[it] = *(const float4*)&A[(size_t)(bm + r) * K + c];
        int kk = l >> 5, n = (l & 31) * 4;
        bReg[it] = *(const float4*)&B[(size_t)kk * N + bn + n];
    }

    for (int k0 = 0; k0 < K; k0 += 32) {
        #pragma unroll
        for (int it = 0; it < 4; it++) {
            int l = tid + it*256;
            int r = l >> 3, c = (l & 7) * 4;
            As[r][c]   = tf32r(aReg[it].x);
            As[r][c+1] = tf32r(aReg[it].y);
            As[r][c+2] = tf32r(aReg[it].z);
            As[r][c+3] = tf32r(aReg[it].w);
            int kk = l >> 5, n = (l & 31) * 4;
            Bs[kk][n]   = tf32r(bReg[it].x);
            Bs[kk][n+1] = tf32r(bReg[it].y);
            Bs[kk][n+2] = tf32r(bReg[it].z);
            Bs[kk][n+3] = tf32r(bReg[it].w);
        }
        __syncthreads();

        if (k0 + 32 < K) {
            #pragma unroll
            for (int it = 0; it < 4; it++) {
                int l = tid + it*256;
                int r = l >> 3, c = (l & 7) * 4;
                aReg[it] = *(const float4*)&A[(size_t)(bm + r) * K + k0 + 32 + c];
                int kk = l >> 5, n = (l & 31) * 4;
                bReg[it] = *(const float4*)&B[(size_t)(k0 + 32 + kk) * N + bn + n];
            }
        }

        #pragma unroll
        for (int ks = 0; ks < 32; ks += 8) {
            uint32_t af[4][4], bf[4][2];
            #pragma unroll
            for (int mi = 0; mi < 4; mi++) {
                int row = wm + mi*16 + qr;
                af[mi][0] = __float_as_uint(As[row  ][ks + qk]);
                af[mi][1] = __float_as_uint(As[row+8][ks + qk]);
                af[mi][2] = __float_as_uint(As[row  ][ks + qk + 4]);
                af[mi][3] = __float_as_uint(As[row+8][ks + qk + 4]);
            }
            #pragma unroll
            for (int ni = 0; ni < 4; ni++) {
                int col = wn + ni*8 + qr;
                bf[ni][0] = __float_as_uint(Bs[ks + qk    ][col]);
                bf[ni][1] = __float_as_uint(Bs[ks + qk + 4][col]);
            }
            #pragma unroll
            for (int mi = 0; mi < 4; mi++)
                #pragma unroll
                for (int ni = 0; ni < 4; ni++)
                    mma1688(acc[mi][ni], af[mi], bf[ni]);
        }
        __syncthreads();
    }

    #pragma unroll
    for (int mi = 0; mi < 4; mi++) {
        #pragma unroll
        for (int ni = 0; ni < 4; ni++) {
            int row0 = bm + wm + mi*16 + qr;
            int col  = bn + wn + ni*8 + qk*2;
            #pragma unroll
            for (int half = 0; half < 2; half++) {
                int row = row0 + half*8;
                float2 v = make_float2(acc[mi][ni][half*2], acc[mi][ni][half*2+1]);
                if (BIAS) { v.x += bias[col]; v.y += bias[col+1]; }
                if (RES) {
                    const float2 rr = *(const float2*)&R[(size_t)row*N + col];
                    v.x += rr.x; v.y += rr.y;
                }
                *(float2*)&C[(size_t)row*N + col] = v;
            }
        }
    }
}

// ---------------- RoPE (double sincos, fast-math-proof) ----------------
__global__ void rope_reorder(const float* __restrict__ q, const float* __restrict__ k,
                             const float* __restrict__ v,
                             float* __restrict__ rq, float* __restrict__ rk,
                             float* __restrict__ vt)
{
    int p = blockIdx.x*256 + threadIdx.x;
    if (p >= Bb*Tt*Hh*32) return;
    int j = p & 31;  int r = p >> 5;
    int h = r % Hh;  r /= Hh;
    int t = r % Tt;  int b = r / Tt;
    size_t in  = ((size_t)(b*Tt + t))*Cc + h*Ss + 2*j;
    size_t out = (((size_t)(b*Hh + h))*Tt + t)*Ss + 2*j;
    double theta = exp(-0.5756462732485115 * (double)j);
    float thf = (float)theta;
    double ang = (double)((float)t * thf);
    double sn, cs;
    sincos(ang, &sn, &cs);
    float csf = (float)cs, snf = (float)sn;
    float q0 = q[in], q1 = q[in+1];
    rq[out]   = q0*csf - q1*snf;
    rq[out+1] = q1*csf + q0*snf;
    float k0 = k[in], k1 = k[in+1];
    rk[out]   = k0*csf - k1*snf;
    rk[out+1] = k1*csf + k0*snf;
    vt[out]   = v[in];
    vt[out+1] = v[in+1];
}

// ---------------- fused flash attention (tf32 MMA + online softmax) ----------------
// block: 128 threads (4 warps), one 64-row Q tile per block. grid (Tt/64, BHn).
// smem strides chosen bank-conflict-free per operand.
#define KSTR 68   // K/P/A-style loads: bank 4*qr+qk (bijective)
#define VSTR 72   // V B-frag loads:    bank 8*qk+qr (bijective)
#define PSTR 68

__global__ __launch_bounds__(128) void flash_attn(
    const float* __restrict__ Q, const float* __restrict__ K,
    const float* __restrict__ V, float* __restrict__ O)
{
    extern __shared__ float sm[];
    float* Ks = sm;                   // 64*KSTR
    float* Vs = Ks + 64*KSTR;         // 64*VSTR
    float* Ps = Vs + 64*VSTR;         // 64*PSTR (also Q staging)

    const int bh = blockIdx.y;
    const int b = bh / Hh, h = bh % Hh;
    const int t0 = blockIdx.x * 64;
    const int tid = threadIdx.x;
    const int lane = tid & 31;
    const int warp = tid >> 5;
    const int wm = warp * 16;
    const int qr = lane >> 2;
    const int qk = lane & 3;

    const float scale = 0.036084391824351615f;  // 768^-0.5 (folded into Q)
    const float* Qg = Q + ((size_t)bh*Tt + t0) * Ss;
    const float* Kg = K + (size_t)bh*Tt*Ss;
    const float* Vg = V + (size_t)bh*Tt*Ss;

    // stage Q (scaled + tf32) then extract per-warp fragments to registers
    #pragma unroll
    for (int it = 0; it < 8; it++) {
        int l = tid + it*128;
        int r = l >> 4, c = (l & 15) * 4;
        float4 v = *(const float4*)(Qg + (size_t)r*Ss + c);
        Ps[r*PSTR + c]   = tf32r(v.x * scale);
        Ps[r*PSTR + c+1] = tf32r(v.y * scale);
        Ps[r*PSTR + c+2] = tf32r(v.z * scale);
        Ps[r*PSTR + c+3] = tf32r(v.w * scale);
    }
    __syncthreads();
    uint32_t qf[8][4];
    #pragma unroll
    for (int ks = 0; ks < 8; ks++) {
        qf[ks][0] = __float_as_uint(Ps[(wm+qr  )*PSTR + ks*8 + qk    ]);
        qf[ks][1] = __float_as_uint(Ps[(wm+qr+8)*PSTR + ks*8 + qk    ]);
        qf[ks][2] = __float_as_uint(Ps[(wm+qr  )*PSTR + ks*8 + qk + 4]);
        qf[ks][3] = __float_as_uint(Ps[(wm+qr+8)*PSTR + ks*8 + qk + 4]);
    }
    __syncthreads();

    float oacc[8][4];
    #pragma unroll
    for (int nt = 0; nt < 8; nt++)
        #pragma unroll
        for (int c = 0; c < 4; c++) oacc[nt][c] = 0.f;
    float mA = -1e30f, mB = -1e30f, lA = 0.f, lB = 0.f;

    const int ktmax = t0 >> 6;
    for (int kt = 0; kt <= ktmax; kt++) {
        // load K/V tiles (tf32)
        #pragma unroll
        for (int it = 0; it < 8; it++) {
            int l = tid + it*128;
            int r = l >> 4, c = (l & 15) * 4;
            float4 kv = *(const float4*)(Kg + (size_t)(kt*64 + r)*Ss + c);
            Ks[r*KSTR + c]   = tf32r(kv.x);
            Ks[r*KSTR + c+1] = tf32r(kv.y);
            Ks[r*KSTR + c+2] = tf32r(kv.z);
            Ks[r*KSTR + c+3] = tf32r(kv.w);
            float4 vv = *(const float4*)(Vg + (size_t)(kt*64 + r)*Ss + c);
            Vs[r*VSTR + c]   = tf32r(vv.x);
            Vs[r*VSTR + c+1] = tf32r(vv.y);
            Vs[r*VSTR + c+2] = tf32r(vv.z);
            Vs[r*VSTR + c+3] = tf32r(vv.w);
        }
        __syncthreads();

        // scores S = Qs·K^T (scaled)
        float sacc[8][4];
        #pragma unroll
        for (int nt = 0; nt < 8; nt++)
            #pragma unroll
            for (int c = 0; c < 4; c++) sacc[nt][c] = 0.f;
        #pragma unroll
        for (int ks = 0; ks < 8; ks++) {
            #pragma unroll
            for (int nt = 0; nt < 8; nt++) {
                uint32_t bf[2];
                bf[0] = __float_as_uint(Ks[(nt*8+qr)*KSTR + ks*8 + qk    ]);
                bf[1] = __float_as_uint(Ks[(nt*8+qr)*KSTR + ks*8 + qk + 4]);
                mma1688(sacc[nt], qf[ks], bf);
            }
        }

        // causal mask on diagonal tile
        if (kt == ktmax) {
            int grA = t0 + wm + qr, grB = grA + 8;
            #pragma unroll
            for (int nt = 0; nt < 8; nt++) {
                int gc = kt*64 + nt*8 + 2*qk;
                if (gc     > grA) sacc[nt][0] = -1e30f;
                if (gc + 1 > grA) sacc[nt][1] = -1e30f;
                if (gc     > grB) sacc[nt][2] = -1e30f;
                if (gc + 1 > grB) sacc[nt][3] = -1e30f;
            }
        }

        // online softmax
        float tmA = -1e30f, tmB = -1e30f;
        #pragma unroll
        for (int nt = 0; nt < 8; nt++) {
            tmA = fmaxf(tmA, fmaxf(sacc[nt][0], sacc[nt][1]));
            tmB = fmaxf(tmB, fmaxf(sacc[nt][2], sacc[nt][3]));
        }
        tmA = fmaxf(tmA, __shfl_xor_sync(0xffffffffu, tmA, 1));
        tmA = fmaxf(tmA, __shfl_xor_sync(0xffffffffu, tmA, 2));
        tmB = fmaxf(tmB, __shfl_xor_sync(0xffffffffu, tmB, 1));
        tmB = fmaxf(tmB, __shfl_xor_sync(0xffffffffu, tmB, 2));
        float mAn = fmaxf(mA, tmA), mBn = fmaxf(mB, tmB);
        float aA = __expf(mA - mAn), aB = __expf(mB - mBn);
        float sA = 0.f, sB = 0.f;
        #pragma unroll
        for (int nt = 0; nt < 8; nt++) {
            float p0 = __expf(sacc[nt][0] - mAn);
            float p1 = __expf(sacc[nt][1] - mAn);
            float p2 = __expf(sacc[nt][2] - mBn);
            float p3 = __expf(sacc[nt][3] - mBn);
            sA += p0 + p1;  sB += p2 + p3;
            Ps[(wm+qr  )*PSTR + nt*8 + 2*qk]     = tf32r(p0);
            Ps[(wm+qr  )*PSTR + nt*8 + 2*qk + 1] = tf32r(p1);
            Ps[(wm+qr+8)*PSTR + nt*8 + 2*qk]     = tf32r(p2);
            Ps[(wm+qr+8)*PSTR + nt*8 + 2*qk + 1] = tf32r(p3);
        }
        sA += __shfl_xor_sync(0xffffffffu, sA, 1);
        sA += __shfl_xor_sync(0xffffffffu, sA, 2);
        sB += __shfl_xor_sync(0xffffffffu, sB, 1);
        sB += __shfl_xor_sync(0xffffffffu, sB, 2);
        lA = lA*aA + sA;  lB = lB*aB + sB;
        mA = mAn;  mB = mBn;
        #pragma unroll
        for (int nt = 0; nt < 8; nt++) {
            oacc[nt][0] *= aA; oacc[nt][1] *= aA;
            oacc[nt][2] *= aB; oacc[nt][3] *= aB;
        }
        __syncwarp();

        // O += P·V
        #pragma unroll
        for (int ks = 0; ks < 8; ks++) {
            uint32_t af[4];
            af[0] = __float_as_uint(Ps[(wm+qr  )*PSTR + ks*8 + qk    ]);
            af[1] = __float_as_uint(Ps[(wm+qr+8)*PSTR + ks*8 + qk    ]);
            af[2] = __float_as_uint(Ps[(wm+qr  )*PSTR + ks*8 + qk + 4]);
            af[3] = __float_as_uint(Ps[(wm+qr+8)*PSTR + ks*8 + qk + 4]);
            #pragma unroll
            for (int nt = 0; nt < 8; nt++) {
                uint32_t bf[2];
                bf[0] = __float_as_uint(Vs[(ks*8+qk  )*VSTR + nt*8 + qr]);
                bf[1] = __float_as_uint(Vs[(ks*8+qk+4)*VSTR + nt*8 + qr]);
                mma1688(oacc[nt], af, bf);
            }
        }
        __syncthreads();
    }

    // epilogue: normalize + write [b,t,(h,s)]
    float ilA = 1.f / lA, ilB = 1.f / lB;
    int rA = t0 + wm + qr, rB = rA + 8;
    #pragma unroll
    for (int nt = 0; nt < 8; nt++) {
        int col = nt*8 + 2*qk;
        size_t oA = ((size_t)(b*Tt + rA))*Cc + h*Ss + col;
        size_t oB = ((size_t)(b*Tt + rB))*Cc + h*Ss + col;
        *(float2*)&O[oA] = make_float2(oacc[nt][0]*ilA, oacc[nt][1]*ilA);
        *(float2*)&O[oB] = make_float2(oacc[nt][2]*ilB, oacc[nt][3]*ilB);
    }
}

// ---------------- SwiGLU (fp32 __expf: ≤3e-6 rel err, safe) ----------------
__global__ void silu_mul(const float* __restrict__ wx, const float* __restrict__ vx,
                         float* __restrict__ out, int n)
{
    int i = blockIdx.x*256 + threadIdx.x;
    if (i < n) {
        float v = vx[i];
        float sig = 1.f / (1.f + __expf(-v));
        out[i] = wx[i] * (v * sig);
    }
}

static float* symaddr(const void* sym)
{
    void* p = nullptr;
    cudaGetSymbolAddress(&p, sym);
    return (float*)p;
}

extern "C" void kernel_launch(void* const* d_in, const int* in_sizes, int n_in,
                              void* d_out, int out_size)
{
    const float* x  = (const float*)d_in[0];
    const float* Wq = (const float*)d_in[1];
    const float* Wk = (const float*)d_in[2];
    const float* Wv = (const float*)d_in[3];
    const float* Wo = (const float*)d_in[4];
    const float* g1 = (const float*)d_in[5];
    const float* g2 = (const float*)d_in[6];
    const float* W1 = (const float*)d_in[7];
    const float* b1 = (const float*)d_in[8];
    const float* Ww = (const float*)d_in[9];
    const float* bw = (const float*)d_in[10];
    const float* Wg = (const float*)d_in[11];
    const float* bg = (const float*)d_in[12];
    const float* Wd = (const float*)d_in[13];
    const float* bd = (const float*)d_in[14];
    const float* W2 = (const float*)d_in[15];
    const float* b2 = (const float*)d_in[16];
    float* out = (float*)d_out;

    float* p_h    = symaddr(g_h);
    float* p_q    = symaddr(g_q);
    float* p_k    = symaddr(g_k);
    float* p_v    = symaddr(g_v);
    float* p_rq   = symaddr(g_rq);
    float* p_rk   = symaddr(g_rk);
    float* p_vt   = symaddr(g_vt);
    float* p_attn = symaddr(g_attn);
    float* p_out1 = symaddr(g_out1);
    float* p_u    = symaddr(g_u);
    float* p_wx   = symaddr(g_wx);
    float* p_vx   = symaddr(g_vx);
    float* p_ff   = symaddr(g_ff);
    float* p_wp   = symaddr(g_wp);
    float* p_part = symaddr(g_part);
    float* p_scal = symaddr(g_scale);

    const float invn = 1.0f / (float)NTOT;
    const int FA_SMEM = (64*KSTR + 64*VSTR + 64*PSTR) * 4;   // 53,248 B
    static bool attr_set = false;
    if (!attr_set) {
        cudaFuncSetAttribute(flash_attn, cudaFuncAttributeMaxDynamicSharedMemorySize, FA_SMEM);
        attr_set = true;
    }

    sumsq_partial<<<1024, 256>>>(x, NTOT, p_part);
    finalize_scale<<<1, 256>>>(p_part, 1024, invn, p_scal);
    apply_rms<<<NTOT/256, 256>>>(x, p_scal, g1, p_h, NTOT);

    pack_qkv<<<(Hh*Cc*Ss + 255)/256, 256>>>(Wq, Wk, Wv, p_wp);
    tgemm128<false,false><<<dim3(Cc/128, Mm/128), 256>>>(p_h, p_wp,           nullptr, nullptr, p_q, Mm, Cc, Cc);
    tgemm128<false,false><<<dim3(Cc/128, Mm/128), 256>>>(p_h, p_wp + Cc*Cc,   nullptr, nullptr, p_k, Mm, Cc, Cc);
    tgemm128<false,false><<<dim3(Cc/128, Mm/128), 256>>>(p_h, p_wp + 2*Cc*Cc, nullptr, nullptr, p_v, Mm, Cc, Cc);
    rope_reorder<<<(Bb*Tt*Hh*32)/256, 256>>>(p_q, p_k, p_v, p_rq, p_rk, p_vt);

    flash_attn<<<dim3(Tt/64, BHn), 128, FA_SMEM>>>(p_rq, p_rk, p_vt, p_attn);
    tgemm128<false,true><<<dim3(Cc/128, Mm/128), 256>>>(p_attn, Wo, nullptr, x, p_out1, Mm, Cc, Cc);

    sumsq_partial<<<1024, 256>>>(p_out1, NTOT, p_part);
    finalize_scale<<<1, 256>>>(p_part, 1024, invn, p_scal);
    apply_rms<<<NTOT/256, 256>>>(p_out1, p_scal, g2, p_h, NTOT);

    tgemm128<true,false><<<dim3(FFf/128, Mm/128), 256>>>(p_h,  W1, b1, nullptr, p_u,  Mm, FFf,  Cc);
    tgemm128<true,false><<<dim3(HIDh/128, Mm/128), 256>>>(p_u, Ww, bw, nullptr, p_wx, Mm, HIDh, FFf);
    tgemm128<true,false><<<dim3(HIDh/128, Mm/128), 256>>>(p_u, Wg, bg, nullptr, p_vx, Mm, HIDh, FFf);
    silu_mul<<<(Mm*HIDh)/256, 256>>>(p_wx, p_vx, p_wx, Mm*HIDh);
    tgemm128<true,false><<<dim3(FFf/128, Mm/128), 256>>>(p_wx, Wd, bd, nullptr, p_ff, Mm, FFf, HIDh);
    tgemm128<true,true><<<dim3(Cc/128, Mm/128), 256>>>(p_ff, W2, b2, p_out1, out, Mm, Cc, FFf);
}

// round 17
// speedup vs baseline: 11.1382x; 1.0070x over previous
#include <cuda_runtime.h>
#include <cuda_bf16.h>
#include <math.h>
#include <stdint.h>

#define Bb   4
#define Tt   1024
#define Cc   768
#define Hh   12
#define Ss   64
#define FFf  3072
#define HIDh 2048
#define Mm   (Bb*Tt)
#define NTOT (Mm*Cc)
#define BHn  (Bb*Hh)
#define QKVN (3*Cc)          // 2304

__device__ float g_h   [Mm*Cc];
__device__ float g_qkv [Mm*QKVN];
__device__ float g_rq  [Mm*Cc];
__device__ float g_rk  [Mm*Cc];
__device__ float g_vt  [Mm*Cc];
__device__ float g_attn[Mm*Cc];
__device__ float g_out1[Mm*Cc];
__device__ float g_u   [Mm*FFf];
__device__ float g_wx  [Mm*HIDh];
__device__ float g_ff  [Mm*FFf];
__device__ float g_wp  [Cc*QKVN];
__device__ float g_part[1024];
__device__ float g_scale[1];

__device__ __forceinline__ float tf32r(float x)
{
    uint32_t u;
    asm("cvt.rna.tf32.f32 %0, %1;" : "=r"(u) : "f"(x));
    return __uint_as_float(u);
}

__device__ __forceinline__ uint32_t tf32u(float x)
{
    uint32_t u;
    asm("cvt.rna.tf32.f32 %0, %1;" : "=r"(u) : "f"(x));
    return u;
}

__device__ __forceinline__ void mma1688(float* c, const uint32_t* a, const uint32_t* b)
{
    asm("mma.sync.aligned.m16n8k8.row.col.f32.tf32.tf32.f32 "
        "{%0,%1,%2,%3}, {%4,%5,%6,%7}, {%8,%9}, {%0,%1,%2,%3};"
        : "+f"(c[0]), "+f"(c[1]), "+f"(c[2]), "+f"(c[3])
        : "r"(a[0]), "r"(a[1]), "r"(a[2]), "r"(a[3]), "r"(b[0]), "r"(b[1]));
}

__device__ __forceinline__ void cpa16(uint32_t s, const void* g)
{
    asm volatile("cp.async.ca.shared.global [%0], [%1], 16;" :: "r"(s), "l"(g));
}

// ---------------- reductions ----------------
__global__ void sumsq_partial(const float* __restrict__ x, int n, float* __restrict__ part)
{
    float s = 0.f;
    for (int i = blockIdx.x*256 + threadIdx.x; i < n; i += gridDim.x*256) {
        float v = x[i]; s += v*v;
    }
    #pragma unroll
    for (int o = 16; o > 0; o >>= 1) s += __shfl_xor_sync(0xffffffffu, s, o);
    __shared__ float sh[8];
    if ((threadIdx.x & 31) == 0) sh[threadIdx.x >> 5] = s;
    __syncthreads();
    if (threadIdx.x == 0) {
        float t = 0.f;
        #pragma unroll
        for (int w = 0; w < 8; w++) t += sh[w];
        part[blockIdx.x] = t;
    }
}

__global__ void finalize_scale(const float* __restrict__ part, int g, float invn, float* __restrict__ scale)
{
    float s = 0.f;
    for (int i = threadIdx.x; i < g; i += 256) s += part[i];
    #pragma unroll
    for (int o = 16; o > 0; o >>= 1) s += __shfl_xor_sync(0xffffffffu, s, o);
    __shared__ float sh[8];
    if ((threadIdx.x & 31) == 0) sh[threadIdx.x >> 5] = s;
    __syncthreads();
    if (threadIdx.x == 0) {
        double t = 0.0;
        for (int w = 0; w < 8; w++) t += (double)sh[w];
        scale[0] = (float)(1.0 / sqrt(1e-6 + t * (double)invn));
    }
}

__global__ void apply_rms(const float* __restrict__ x, const float* __restrict__ scale,
                          const float* __restrict__ g, float* __restrict__ out, int n)
{
    int i = blockIdx.x*256 + threadIdx.x;
    if (i < n) out[i] = x[i] * scale[0] * g[i % Cc];
}

// pack W_{q,k,v}: [H,C,S] x3 -> one [C, 2304] matrix (q|k|v blocks)
__global__ void pack_qkv(const float* __restrict__ Wq, const float* __restrict__ Wk,
                         const float* __restrict__ Wv, float* __restrict__ Wp)
{
    int i = blockIdx.x*256 + threadIdx.x;
    const int n = Hh*Cc*Ss;
    if (i >= n) return;
    int s = i % Ss; int r = i / Ss; int c = r % Cc; int h = r / Cc;
    int base = c*QKVN + h*Ss + s;
    Wp[base]          = Wq[i];
    Wp[base + Cc]     = Wk[i];
    Wp[base + 2*Cc]   = Wv[i];
}

// ---------------- cp.async double-buffered tf32 GEMM ----------------
#define ASTR 36
#define BSTR 136
#define TG_SMEM ((2*(128*ASTR) + 2*(32*BSTR)) * 4)

template<bool BIAS, bool RES, bool SILU>
__global__ __launch_bounds__(256) void tgemm128(
    const float* __restrict__ A, const float* __restrict__ B,
    const float* __restrict__ bias, const float* __restrict__ R,
    float* __restrict__ C, int M, int N, int K)
{
    extern __shared__ float sm[];
    float* As = sm;                       // [2][128][ASTR]
    float* Bs = sm + 2*128*ASTR;          // [2][32][BSTR]
    const uint32_t sbase = (uint32_t)__cvta_generic_to_shared(sm);
    const uint32_t aoff  = 0;
    const uint32_t boff  = 2*128*ASTR*4;

    const int tid  = threadIdx.x;
    const int lane = tid & 31;
    const int warp = tid >> 5;
    const int wm = (warp >> 2) * 64;
    const int wn = (warp & 3) * 32;
    const int bm = blockIdx.y * 128;
    const int bn = blockIdx.x * 128;
    const int qr = lane >> 2;
    const int qk = lane & 3;

    float acc[4][4][4];
    #pragma unroll
    for (int mi = 0; mi < 4; mi++)
        #pragma unroll
        for (int ni = 0; ni < 4; ni++)
            #pragma unroll
            for (int c = 0; c < 4; c++) acc[mi][ni][c] = 0.f;

    // async tile loader
    auto loadTile = [&](int buf, int k0) {
        #pragma unroll
        for (int it = 0; it < 4; it++) {
            int l = tid + it*256;
            int r = l >> 3, c = (l & 7) * 4;
            cpa16(sbase + aoff + (uint32_t)((buf*128 + r)*ASTR + c)*4,
                  &A[(size_t)(bm + r) * K + k0 + c]);
            int kk = l >> 5, n = (l & 31) * 4;
            cpa16(sbase + boff + (uint32_t)((buf*32 + kk)*BSTR + n)*4,
                  &B[(size_t)(k0 + kk) * N + bn + n]);
        }
        asm volatile("cp.async.commit_group;");
    };

    loadTile(0, 0);
    int buf = 0;
    for (int k0 = 0; k0 < K; k0 += 32) {
        asm volatile("cp.async.wait_group 0;");
        __syncthreads();
        if (k0 + 32 < K) loadTile(buf ^ 1, k0 + 32);

        const float* Ab = As + buf*128*ASTR;
        const float* Bbf = Bs + buf*32*BSTR;
        #pragma unroll
        for (int ks = 0; ks < 32; ks += 8) {
            uint32_t af[4][4], bf[4][2];
            #pragma unroll
            for (int mi = 0; mi < 4; mi++) {
                int row = wm + mi*16 + qr;
                af[mi][0] = tf32u(Ab[row*ASTR + ks + qk]);
                af[mi][1] = tf32u(Ab[(row+8)*ASTR + ks + qk]);
                af[mi][2] = tf32u(Ab[row*ASTR + ks + qk + 4]);
                af[mi][3] = tf32u(Ab[(row+8)*ASTR + ks + qk + 4]);
            }
            #pragma unroll
            for (int ni = 0; ni < 4; ni++) {
                int col = wn + ni*8 + qr;
                bf[ni][0] = tf32u(Bbf[(ks + qk)*BSTR + col]);
                bf[ni][1] = tf32u(Bbf[(ks + qk + 4)*BSTR + col]);
            }
            #pragma unroll
            for (int mi = 0; mi < 4; mi++)
                #pragma unroll
                for (int ni = 0; ni < 4; ni++)
                    mma1688(acc[mi][ni], af[mi], bf[ni]);
        }
        buf ^= 1;
        __syncthreads();
    }

    #pragma unroll
    for (int mi = 0; mi < 4; mi++) {
        #pragma unroll
        for (int ni = 0; ni < 4; ni++) {
            int row0 = bm + wm + mi*16 + qr;
            int col  = bn + wn + ni*8 + qk*2;
            #pragma unroll
            for (int half = 0; half < 2; half++) {
                int row = row0 + half*8;
                float2 v = make_float2(acc[mi][ni][half*2], acc[mi][ni][half*2+1]);
                if (BIAS) { v.x += bias[col]; v.y += bias[col+1]; }
                if (SILU) {
                    const float2 wx = *(const float2*)&R[(size_t)row*N + col];
                    v.x = wx.x * (v.x * (1.f / (1.f + __expf(-v.x))));
                    v.y = wx.y * (v.y * (1.f / (1.f + __expf(-v.y))));
                } else if (RES) {
                    const float2 rr = *(const float2*)&R[(size_t)row*N + col];
                    v.x += rr.x; v.y += rr.y;
                }
                *(float2*)&C[(size_t)row*N + col] = v;
            }
        }
    }
}

// ---------------- RoPE (reads fused qkv [m][2304]) ----------------
__global__ void rope_reorder(const float* __restrict__ qkv,
                             float* __restrict__ rq, float* __restrict__ rk,
                             float* __restrict__ vt)
{
    int p = blockIdx.x*256 + threadIdx.x;
    if (p >= Bb*Tt*Hh*32) return;
    int j = p & 31;  int r = p >> 5;
    int h = r % Hh;  r /= Hh;
    int t = r % Tt;  int b = r / Tt;
    size_t in  = ((size_t)(b*Tt + t))*QKVN + h*Ss + 2*j;
    size_t out = (((size_t)(b*Hh + h))*Tt + t)*Ss + 2*j;
    double theta = exp(-0.5756462732485115 * (double)j);
    float thf = (float)theta;
    double ang = (double)((float)t * thf);
    double sn, cs;
    sincos(ang, &sn, &cs);
    float csf = (float)cs, snf = (float)sn;
    float q0 = qkv[in], q1 = qkv[in+1];
    rq[out]   = q0*csf - q1*snf;
    rq[out+1] = q1*csf + q0*snf;
    float k0 = qkv[in+Cc], k1 = qkv[in+Cc+1];
    rk[out]   = k0*csf - k1*snf;
    rk[out+1] = k1*csf + k0*snf;
    vt[out]   = qkv[in+2*Cc];
    vt[out+1] = qkv[in+2*Cc+1];
}

// ---------------- fused flash attention (R16, unchanged) ----------------
#define KSTR 68
#define VSTR 72
#define PSTR 68

__global__ __launch_bounds__(128) void flash_attn(
    const float* __restrict__ Q, const float* __restrict__ K,
    const float* __restrict__ V, float* __restrict__ O)
{
    extern __shared__ float sm[];
    float* Ks = sm;
    float* Vs = Ks + 64*KSTR;
    float* Ps = Vs + 64*VSTR;

    const int bh = blockIdx.y;
    const int b = bh / Hh, h = bh % Hh;
    const int t0 = blockIdx.x * 64;
    const int tid = threadIdx.x;
    const int lane = tid & 31;
    const int warp = tid >> 5;
    const int wm = warp * 16;
    const int qr = lane >> 2;
    const int qk = lane & 3;

    const float scale = 0.036084391824351615f;
    const float* Qg = Q + ((size_t)bh*Tt + t0) * Ss;
    const float* Kg = K + (size_t)bh*Tt*Ss;
    const float* Vg = V + (size_t)bh*Tt*Ss;

    #pragma unroll
    for (int it = 0; it < 8; it++) {
        int l = tid + it*128;
        int r = l >> 4, c = (l & 15) * 4;
        float4 v = *(const float4*)(Qg + (size_t)r*Ss + c);
        Ps[r*PSTR + c]   = tf32r(v.x * scale);
        Ps[r*PSTR + c+1] = tf32r(v.y * scale);
        Ps[r*PSTR + c+2] = tf32r(v.z * scale);
        Ps[r*PSTR + c+3] = tf32r(v.w * scale);
    }
    __syncthreads();
    uint32_t qf[8][4];
    #pragma unroll
    for (int ks = 0; ks < 8; ks++) {
        qf[ks][0] = __float_as_uint(Ps[(wm+qr  )*PSTR + ks*8 + qk    ]);
        qf[ks][1] = __float_as_uint(Ps[(wm+qr+8)*PSTR + ks*8 + qk    ]);
        qf[ks][2] = __float_as_uint(Ps[(wm+qr  )*PSTR + ks*8 + qk + 4]);
        qf[ks][3] = __float_as_uint(Ps[(wm+qr+8)*PSTR + ks*8 + qk + 4]);
    }
    __syncthreads();

    float oacc[8][4];
    #pragma unroll
    for (int nt = 0; nt < 8; nt++)
        #pragma unroll
        for (int c = 0; c < 4; c++) oacc[nt][c] = 0.f;
    float mA = -1e30f, mB = -1e30f, lA = 0.f, lB = 0.f;

    const int ktmax = t0 >> 6;
    for (int kt = 0; kt <= ktmax; kt++) {
        #pragma unroll
        for (int it = 0; it < 8; it++) {
            int l = tid + it*128;
            int r = l >> 4, c = (l & 15) * 4;
            float4 kv = *(const float4*)(Kg + (size_t)(kt*64 + r)*Ss + c);
            Ks[r*KSTR + c]   = tf32r(kv.x);
            Ks[r*KSTR + c+1] = tf32r(kv.y);
            Ks[r*KSTR + c+2] = tf32r(kv.z);
            Ks[r*KSTR + c+3] = tf32r(kv.w);
            float4 vv = *(const float4*)(Vg + (size_t)(kt*64 + r)*Ss + c);
            Vs[r*VSTR + c]   = tf32r(vv.x);
            Vs[r*VSTR + c+1] = tf32r(vv.y);
            Vs[r*VSTR + c+2] = tf32r(vv.z);
            Vs[r*VSTR + c+3] = tf32r(vv.w);
        }
        __syncthreads();

        float sacc[8][4];
        #pragma unroll
        for (int nt = 0; nt < 8; nt++)
            #pragma unroll
            for (int c = 0; c < 4; c++) sacc[nt][c] = 0.f;
        #pragma unroll
        for (int ks = 0; ks < 8; ks++) {
            #pragma unroll
            for (int nt = 0; nt < 8; nt++) {
                uint32_t bf[2];
                bf[0] = __float_as_uint(Ks[(nt*8+qr)*KSTR + ks*8 + qk    ]);
                bf[1] = __float_as_uint(Ks[(nt*8+qr)*KSTR + ks*8 + qk + 4]);
                mma1688(sacc[nt], qf[ks], bf);
            }
        }

        if (kt == ktmax) {
            int grA = t0 + wm + qr, grB = grA + 8;
            #pragma unroll
            for (int nt = 0; nt < 8; nt++) {
                int gc = kt*64 + nt*8 + 2*qk;
                if (gc     > grA) sacc[nt][0] = -1e30f;
                if (gc + 1 > grA) sacc[nt][1] = -1e30f;
                if (gc     > grB) sacc[nt][2] = -1e30f;
                if (gc + 1 > grB) sacc[nt][3] = -1e30f;
            }
        }

        float tmA = -1e30f, tmB = -1e30f;
        #pragma unroll
        for (int nt = 0; nt < 8; nt++) {
            tmA = fmaxf(tmA, fmaxf(sacc[nt][0], sacc[nt][1]));
            tmB = fmaxf(tmB, fmaxf(sacc[nt][2], sacc[nt][3]));
        }
        tmA = fmaxf(tmA, __shfl_xor_sync(0xffffffffu, tmA, 1));
        tmA = fmaxf(tmA, __shfl_xor_sync(0xffffffffu, tmA, 2));
        tmB = fmaxf(tmB, __shfl_xor_sync(0xffffffffu, tmB, 1));
        tmB = fmaxf(tmB, __shfl_xor_sync(0xffffffffu, tmB, 2));
        float mAn = fmaxf(mA, tmA), mBn = fmaxf(mB, tmB);
        float aA = __expf(mA - mAn), aB = __expf(mB - mBn);
        float sA = 0.f, sB = 0.f;
        #pragma unroll
        for (int nt = 0; nt < 8; nt++) {
            float p0 = __expf(sacc[nt][0] - mAn);
            float p1 = __expf(sacc[nt][1] - mAn);
            float p2 = __expf(sacc[nt][2] - mBn);
            float p3 = __expf(sacc[nt][3] - mBn);
            sA += p0 + p1;  sB += p2 + p3;
            Ps[(wm+qr  )*PSTR + nt*8 + 2*qk]     = tf32r(p0);
            Ps[(wm+qr  )*PSTR + nt*8 + 2*qk + 1] = tf32r(p1);
            Ps[(wm+qr+8)*PSTR + nt*8 + 2*qk]     = tf32r(p2);
            Ps[(wm+qr+8)*PSTR + nt*8 + 2*qk + 1] = tf32r(p3);
        }
        sA += __shfl_xor_sync(0xffffffffu, sA, 1);
        sA += __shfl_xor_sync(0xffffffffu, sA, 2);
        sB += __shfl_xor_sync(0xffffffffu, sB, 1);
        sB += __shfl_xor_sync(0xffffffffu, sB, 2);
        lA = lA*aA + sA;  lB = lB*aB + sB;
        mA = mAn;  mB = mBn;
        #pragma unroll
        for (int nt = 0; nt < 8; nt++) {
            oacc[nt][0] *= aA; oacc[nt][1] *= aA;
            oacc[nt][2] *= aB; oacc[nt][3] *= aB;
        }
        __syncwarp();

        #pragma unroll
        for (int ks = 0; ks < 8; ks++) {
            uint32_t af[4];
            af[0] = __float_as_uint(Ps[(wm+qr  )*PSTR + ks*8 + qk    ]);
            af[1] = __float_as_uint(Ps[(wm+qr+8)*PSTR + ks*8 + qk    ]);
            af[2] = __float_as_uint(Ps[(wm+qr  )*PSTR + ks*8 + qk + 4]);
            af[3] = __float_as_uint(Ps[(wm+qr+8)*PSTR + ks*8 + qk + 4]);
            #pragma unroll
            for (int nt = 0; nt < 8; nt++) {
                uint32_t bf[2];
                bf[0] = __float_as_uint(Vs[(ks*8+qk  )*VSTR + nt*8 + qr]);
                bf[1] = __float_as_uint(Vs[(ks*8+qk+4)*VSTR + nt*8 + qr]);
                mma1688(oacc[nt], af, bf);
            }
        }
        __syncthreads();
    }

    float ilA = 1.f / lA, ilB = 1.f / lB;
    int rA = t0 + wm + qr, rB = rA + 8;
    #pragma unroll
    for (int nt = 0; nt < 8; nt++) {
        int col = nt*8 + 2*qk;
        size_t oA = ((size_t)(b*Tt + rA))*Cc + h*Ss + col;
        size_t oB = ((size_t)(b*Tt + rB))*Cc + h*Ss + col;
        *(float2*)&O[oA] = make_float2(oacc[nt][0]*ilA, oacc[nt][1]*ilA);
        *(float2*)&O[oB] = make_float2(oacc[nt][2]*ilB, oacc[nt][3]*ilB);
    }
}

static float* symaddr(const void* sym)
{
    void* p = nullptr;
    cudaGetSymbolAddress(&p, sym);
    return (float*)p;
}

extern "C" void kernel_launch(void* const* d_in, const int* in_sizes, int n_in,
                              void* d_out, int out_size)
{
    const float* x  = (const float*)d_in[0];
    const float* Wq = (const float*)d_in[1];
    const float* Wk = (const float*)d_in[2];
    const float* Wv = (const float*)d_in[3];
    const float* Wo = (const float*)d_in[4];
    const float* g1 = (const float*)d_in[5];
    const float* g2 = (const float*)d_in[6];
    const float* W1 = (const float*)d_in[7];
    const float* b1 = (const float*)d_in[8];
    const float* Ww = (const float*)d_in[9];
    const float* bw = (const float*)d_in[10];
    const float* Wg = (const float*)d_in[11];
    const float* bg = (const float*)d_in[12];
    const float* Wd = (const float*)d_in[13];
    const float* bd = (const float*)d_in[14];
    const float* W2 = (const float*)d_in[15];
    const float* b2 = (const float*)d_in[16];
    float* out = (float*)d_out;

    float* p_h    = symaddr(g_h);
    float* p_qkv  = symaddr(g_qkv);
    float* p_rq   = symaddr(g_rq);
    float* p_rk   = symaddr(g_rk);
    float* p_vt   = symaddr(g_vt);
    float* p_attn = symaddr(g_attn);
    float* p_out1 = symaddr(g_out1);
    float* p_u    = symaddr(g_u);
    float* p_wx   = symaddr(g_wx);
    float* p_ff   = symaddr(g_ff);
    float* p_wp   = symaddr(g_wp);
    float* p_part = symaddr(g_part);
    float* p_scal = symaddr(g_scale);

    const float invn = 1.0f / (float)NTOT;
    const int FA_SMEM = (64*KSTR + 64*VSTR + 64*PSTR) * 4;

    static bool attr_set = false;
    if (!attr_set) {
        cudaFuncSetAttribute(flash_attn, cudaFuncAttributeMaxDynamicSharedMemorySize, FA_SMEM);
        cudaFuncSetAttribute(tgemm128<false,false,false>, cudaFuncAttributeMaxDynamicSharedMemorySize, TG_SMEM);
        cudaFuncSetAttribute(tgemm128<false,true,false>,  cudaFuncAttributeMaxDynamicSharedMemorySize, TG_SMEM);
        cudaFuncSetAttribute(tgemm128<true,false,false>,  cudaFuncAttributeMaxDynamicSharedMemorySize, TG_SMEM);
        cudaFuncSetAttribute(tgemm128<true,false,true>,   cudaFuncAttributeMaxDynamicSharedMemorySize, TG_SMEM);
        cudaFuncSetAttribute(tgemm128<true,true,false>,   cudaFuncAttributeMaxDynamicSharedMemorySize, TG_SMEM);
        attr_set = true;
    }

    // rms1
    sumsq_partial<<<1024, 256>>>(x, NTOT, p_part);
    finalize_scale<<<1, 256>>>(p_part, 1024, invn, p_scal);
    apply_rms<<<NTOT/256, 256>>>(x, p_scal, g1, p_h, NTOT);

    // fused QKV GEMM
    pack_qkv<<<(Hh*Cc*Ss + 255)/256, 256>>>(Wq, Wk, Wv, p_wp);
    tgemm128<false,false,false><<<dim3(QKVN/128, Mm/128), 256, TG_SMEM>>>(p_h, p_wp, nullptr, nullptr, p_qkv, Mm, QKVN, Cc);
    rope_reorder<<<(Bb*Tt*Hh*32)/256, 256>>>(p_qkv, p_rq, p_rk, p_vt);

    // attention
    flash_attn<<<dim3(Tt/64, BHn), 128, FA_SMEM>>>(p_rq, p_rk, p_vt, p_attn);
    tgemm128<false,true,false><<<dim3(Cc/128, Mm/128), 256, TG_SMEM>>>(p_attn, Wo, nullptr, x, p_out1, Mm, Cc, Cc);

    // rms2
    sumsq_partial<<<1024, 256>>>(p_out1, NTOT, p_part);
    finalize_scale<<<1, 256>>>(p_part, 1024, invn, p_scal);
    apply_rms<<<NTOT/256, 256>>>(p_out1, p_scal, g2, p_h, NTOT);

    // MLP (silu fused into Wg epilogue)
    tgemm128<true,false,false><<<dim3(FFf/128, Mm/128), 256, TG_SMEM>>>(p_h,  W1, b1, nullptr, p_u,  Mm, FFf,  Cc);
    tgemm128<true,false,false><<<dim3(HIDh/128, Mm/128), 256, TG_SMEM>>>(p_u, Ww, bw, nullptr, p_wx, Mm, HIDh, FFf);
    tgemm128<true,false,true ><<<dim3(HIDh/128, Mm/128), 256, TG_SMEM>>>(p_u, Wg, bg, p_wx,    p_wx, Mm, HIDh, FFf);
    tgemm128<true,false,false><<<dim3(FFf/128, Mm/128), 256, TG_SMEM>>>(p_wx, Wd, bd, nullptr, p_ff, Mm, FFf, HIDh);
    tgemm128<true,true,false ><<<dim3(Cc/128, Mm/128), 256, TG_SMEM>>>(p_ff, W2, b2, p_out1, out, Mm, Cc, FFf);
}